// round 10
// baseline (speedup 1.0000x reference)
#include <cuda_runtime.h>
#include <cuda_bf16.h>
#include <math.h>

#define NEG_SLOPE 0.2f

// ---------------- device scratch (no allocations allowed) ----------------
#define NMAX 50000
#define ETOTMAX 850000
#define SCANBLK 256
#define MAXSB 1024

__device__ float g_bufA[NMAX * 64];
__device__ float g_bufB[NMAX * 64];
__device__ float g_as[NMAX];
__device__ float g_ad[NMAX];
__device__ int   g_count[NMAX];
__device__ int   g_rowstart[NMAX + 1];
__device__ int   g_cursor[NMAX];
__device__ int   g_srcsorted[ETOTMAX];
__device__ int   g_blocksum[MAXSB];
__device__ int   g_blockoff[MAXSB];
__device__ int   g_idx64;
__device__ __nv_bfloat16 g_w1hi[64 * 768];
__device__ __nv_bfloat16 g_w1lo[64 * 768];
__device__ __nv_bfloat16 g_w2hi[64 * 64];
__device__ __nv_bfloat16 g_w2lo[64 * 64];

__device__ __forceinline__ float* bufsel(int id) { return id == 0 ? g_bufA : g_bufB; }

__device__ __forceinline__ int loadIdx(const void* p, long long i, int is64) {
    if (is64) return (int)((const long long*)p)[i];
    return ((const int*)p)[i];
}

// packed f32x2 -> bf16x2 (first arg lands in upper 16 bits, second in lower)
__device__ __forceinline__ unsigned cvt2bf(float hi, float lo) {
    unsigned r;
    asm("cvt.rn.bf16x2.f32 %0, %1, %2;" : "=r"(r) : "f"(hi), "f"(lo));
    return r;
}
__device__ __forceinline__ float bf_lo_as_f32(unsigned p) { return __uint_as_float(p << 16); }
__device__ __forceinline__ float bf_hi_as_f32(unsigned p) { return __uint_as_float(p & 0xFFFF0000u); }

// bf16 tensor-core MMA (sm_80+ path; compiles under compute_103)
__device__ __forceinline__ void mma_bf16(float* c, const unsigned* a, const unsigned* b) {
    asm volatile(
        "mma.sync.aligned.m16n8k16.row.col.f32.bf16.bf16.f32 "
        "{%0,%1,%2,%3}, {%4,%5,%6,%7}, {%8,%9}, {%0,%1,%2,%3};"
        : "+f"(c[0]), "+f"(c[1]), "+f"(c[2]), "+f"(c[3])
        : "r"(a[0]), "r"(a[1]), "r"(a[2]), "r"(a[3]), "r"(b[0]), "r"(b[1]));
}

// ---------------- zero counts + dtype probe (fused) ----------------
__global__ void zero_detect_kernel(const void* __restrict__ batch, int N) {
    int i = blockIdx.x * blockDim.x + threadIdx.x;
    if (i < N) g_count[i] = 0;
    if (blockIdx.x == 0) {
        __shared__ int nz;
        if (threadIdx.x == 0) nz = 0;
        __syncthreads();
        const int* w = (const int*)batch;
        int local = 0;
        for (int j = 1 + 2 * threadIdx.x; j < N; j += 2 * blockDim.x)
            if (w[j] != 0) local = 1;
        if (local) atomicOr(&nz, 1);
        __syncthreads();
        if (threadIdx.x == 0) g_idx64 = (nz == 0) ? 1 : 0;
    }
}

// ---------------- graph build ----------------
__global__ void hist_kernel(const void* __restrict__ ei, int E, int N) {
    int i = blockIdx.x * blockDim.x + threadIdx.x;
    int tot = E + N;
    if (i >= tot) return;
    int is64 = g_idx64;
    int dst = (i < E) ? loadIdx(ei, (long long)E + i, is64) : (i - E);
    atomicAdd(&g_count[dst], 1);
}

__global__ void partial_scan_kernel(int N) {
    __shared__ int wsum[8];
    int t = threadIdx.x;
    int idx = blockIdx.x * SCANBLK + t;
    int v = (idx < N) ? g_count[idx] : 0;
    int lane = t & 31, w = t >> 5;
    int s = v;
#pragma unroll
    for (int o = 1; o < 32; o <<= 1) {
        int u = __shfl_up_sync(0xffffffffu, s, o);
        if (lane >= o) s += u;
    }
    if (lane == 31) wsum[w] = s;
    __syncthreads();
    if (w == 0) {
        int ws = (lane < 8) ? wsum[lane] : 0;
#pragma unroll
        for (int o = 1; o < 8; o <<= 1) {
            int u = __shfl_up_sync(0xffffffffu, ws, o);
            if (lane >= o) ws += u;
        }
        if (lane < 8) wsum[lane] = ws;
    }
    __syncthreads();
    int incl = s + (w > 0 ? wsum[w - 1] : 0);
    if (idx < N) g_rowstart[idx] = incl - v;
    if (t == SCANBLK - 1) g_blocksum[blockIdx.x] = incl;
}

__global__ void scan_sums_kernel(int nb) {
    __shared__ int wsum[32];
    int t = threadIdx.x;
    int lane = t & 31, w = t >> 5;
    int v = (t < nb) ? g_blocksum[t] : 0;
    int s = v;
#pragma unroll
    for (int o = 1; o < 32; o <<= 1) {
        int u = __shfl_up_sync(0xffffffffu, s, o);
        if (lane >= o) s += u;
    }
    if (lane == 31) wsum[w] = s;
    __syncthreads();
    if (w == 0) {
        int ws = wsum[lane];
#pragma unroll
        for (int o = 1; o < 32; o <<= 1) {
            int u = __shfl_up_sync(0xffffffffu, ws, o);
            if (lane >= o) ws += u;
        }
        wsum[lane] = ws;
    }
    __syncthreads();
    int excl = s - v + (w > 0 ? wsum[w - 1] : 0);
    if (t < nb) g_blockoff[t] = excl;
}

__global__ void add_off_kernel(int N, int tot) {
    int idx = blockIdx.x * blockDim.x + threadIdx.x;
    if (idx < N) {
        int r = g_rowstart[idx] + g_blockoff[idx >> 8];
        g_rowstart[idx] = r;
        g_cursor[idx] = r;
    }
    if (idx == 0) g_rowstart[N] = tot;
}

__global__ void scatter_kernel(const void* __restrict__ ei, int E, int N) {
    int i = blockIdx.x * blockDim.x + threadIdx.x;
    int tot = E + N;
    if (i >= tot) return;
    int is64 = g_idx64;
    int src, dst;
    if (i < E) {
        src = loadIdx(ei, i, is64);
        dst = loadIdx(ei, (long long)E + i, is64);
    } else {
        src = i - E; dst = i - E;
    }
    int pos = atomicAdd(&g_cursor[dst], 1);
    g_srcsorted[pos] = src;
}

// ---------------- W prep (fused W1+W2): transpose + bf16 hi/lo split ----------------
#define W1ELEMS (768 * 64)
#define W2ELEMS (64 * 64)
__global__ void wprep_both_kernel(const float* __restrict__ W1, const float* __restrict__ W2) {
    int t = blockIdx.x * blockDim.x + threadIdx.x;
    if (t < W1ELEMS) {
        int k = t >> 6, n = t & 63;
        float v = W1[t];
        __nv_bfloat16 hi = __float2bfloat16(v);
        __nv_bfloat16 lo = __float2bfloat16(v - __bfloat162float(hi));
        g_w1hi[n * 768 + k] = hi;
        g_w1lo[n * 768 + k] = lo;
    } else if (t < W1ELEMS + W2ELEMS) {
        int u = t - W1ELEMS;
        int k = u >> 6, n = u & 63;
        float v = W2[u];
        __nv_bfloat16 hi = __float2bfloat16(v);
        __nv_bfloat16 lo = __float2bfloat16(v - __bfloat162float(hi));
        g_w2hi[n * 64 + k] = hi;
        g_w2lo[n * 64 + k] = lo;
    }
}

// ---------------- GEMM via mma.sync bf16x3 + fused attention scores ----------------
// H[N,64] = X[N,NKC*64] @ W; also writes g_as = H@att_s, g_ad = H@att_d.
// 256 threads, 8 warps as 4(m) x 2(n); block tile 128x64; K chunks of 64.
// occ 3 (single wave at N=50000): W loaded directly in stage (L2-hot), only X prefetched.
#define ASTR 144
#define G1SMEM (2 * 128 * ASTR + 2 * 64 * ASTR)   // 55296 B

template <int NKC, int XB, int DB, int WSel>
__global__ void __launch_bounds__(256, 3) gemm_mma_kernel(const float* __restrict__ Xext,
                                                          const float* __restrict__ att_s,
                                                          const float* __restrict__ att_d,
                                                          int nrows) {
    extern __shared__ char sm[];
    char* sAh = sm;
    char* sAl = sm + 128 * ASTR;
    char* sBh = sm + 2 * 128 * ASTR;
    char* sBl = sBh + 64 * ASTR;

    const int t = threadIdx.x;
    const int lane = t & 31, wid = t >> 5;
    const int g = lane >> 2, tg = lane & 3;
    const int wm = wid >> 1, wn = wid & 1;
    const int row0 = blockIdx.x * 128;

    const float* X = (XB < 0) ? Xext : bufsel(XB);
    float* OutBuf = bufsel(DB);
    const float4* X4 = (const float4*)X;
    const uint2* WH = (const uint2*)((WSel == 1) ? g_w1hi : g_w2hi);
    const uint2* WL = (const uint2*)((WSel == 1) ? g_w1lo : g_w2lo);

    float acc[2][4][4];
#pragma unroll
    for (int a = 0; a < 2; a++)
#pragma unroll
        for (int b = 0; b < 4; b++)
#pragma unroll
            for (int c = 0; c < 4; c++) acc[a][b][c] = 0.f;

    float4 px[8];

    auto loadX = [&](int kc) {
#pragma unroll
        for (int i = 0; i < 8; i++) {
            int idx = t + i * 256, r = idx >> 4, q = idx & 15;
            px[i] = (row0 + r < nrows) ? X4[(size_t)(row0 + r) * (NKC * 16) + kc * 16 + q]
                                       : make_float4(0.f, 0.f, 0.f, 0.f);
        }
    };
    auto stage = [&](int kc) {
#pragma unroll
        for (int i = 0; i < 8; i++) {
            int idx = t + i * 256, r = idx >> 4, q = idx & 15;
            float4 v = px[i];
            unsigned h01 = cvt2bf(v.y, v.x);
            unsigned h23 = cvt2bf(v.w, v.z);
            float l0 = v.x - bf_lo_as_f32(h01);
            float l1 = v.y - bf_hi_as_f32(h01);
            float l2 = v.z - bf_lo_as_f32(h23);
            float l3 = v.w - bf_hi_as_f32(h23);
            unsigned l01 = cvt2bf(l1, l0);
            unsigned l23 = cvt2bf(l3, l2);
            *(uint2*)(sAh + r * ASTR + q * 8) = make_uint2(h01, h23);
            *(uint2*)(sAl + r * ASTR + q * 8) = make_uint2(l01, l23);
        }
        // W tiles loaded directly from global (L2-hot after first CTA)
#pragma unroll
        for (int i = 0; i < 4; i++) {
            int idx = t + i * 256, n = idx >> 4, q = idx & 15;
            *(uint2*)(sBh + n * ASTR + q * 8) = WH[n * (NKC * 16) + kc * 16 + q];
            *(uint2*)(sBl + n * ASTR + q * 8) = WL[n * (NKC * 16) + kc * 16 + q];
        }
    };

    loadX(0);
    for (int kc = 0; kc < NKC; kc++) {
        stage(kc);
        __syncthreads();
        if (kc < NKC - 1) loadX(kc + 1);
#pragma unroll
        for (int ks = 0; ks < 4; ks++) {
            unsigned ah[2][4], al[2][4];
#pragma unroll
            for (int mf = 0; mf < 2; mf++) {
                int roff = (wm * 32 + mf * 16 + g) * ASTR + ks * 32 + tg * 4;
                ah[mf][0] = *(const unsigned*)(sAh + roff);
                ah[mf][1] = *(const unsigned*)(sAh + roff + 8 * ASTR);
                ah[mf][2] = *(const unsigned*)(sAh + roff + 16);
                ah[mf][3] = *(const unsigned*)(sAh + roff + 8 * ASTR + 16);
                al[mf][0] = *(const unsigned*)(sAl + roff);
                al[mf][1] = *(const unsigned*)(sAl + roff + 8 * ASTR);
                al[mf][2] = *(const unsigned*)(sAl + roff + 16);
                al[mf][3] = *(const unsigned*)(sAl + roff + 8 * ASTR + 16);
            }
#pragma unroll
            for (int nf = 0; nf < 4; nf++) {
                int noff = (wn * 32 + nf * 8 + g) * ASTR + ks * 32 + tg * 4;
                unsigned bh[2], bl[2];
                bh[0] = *(const unsigned*)(sBh + noff);
                bh[1] = *(const unsigned*)(sBh + noff + 16);
                bl[0] = *(const unsigned*)(sBl + noff);
                bl[1] = *(const unsigned*)(sBl + noff + 16);
#pragma unroll
                for (int mf = 0; mf < 2; mf++) {
                    mma_bf16(acc[mf][nf], ah[mf], bh);
                    mma_bf16(acc[mf][nf], ah[mf], bl);
                    mma_bf16(acc[mf][nf], al[mf], bh);
                }
            }
        }
        __syncthreads();
    }

    // ---- epilogue: store D + fused attention scores ----
    float asc[8], adc[8];
#pragma unroll
    for (int nf = 0; nf < 4; nf++) {
        int c = wn * 32 + nf * 8 + tg * 2;
        asc[nf * 2] = att_s[c]; asc[nf * 2 + 1] = att_s[c + 1];
        adc[nf * 2] = att_d[c]; adc[nf * 2 + 1] = att_d[c + 1];
    }
    float* fS = (float*)sm;          // [128][2]
    float* fD = (float*)sm + 256;    // [128][2]

#pragma unroll
    for (int mf = 0; mf < 2; mf++) {
        int rbase = row0 + wm * 32 + mf * 16;
#pragma unroll
        for (int h = 0; h < 2; h++) {
            int r = rbase + g + h * 8;
            float ps = 0.f, pd = 0.f;
#pragma unroll
            for (int nf = 0; nf < 4; nf++) {
                float v0 = acc[mf][nf][h * 2], v1 = acc[mf][nf][h * 2 + 1];
                ps += v0 * asc[nf * 2] + v1 * asc[nf * 2 + 1];
                pd += v0 * adc[nf * 2] + v1 * adc[nf * 2 + 1];
            }
            ps += __shfl_xor_sync(0xffffffffu, ps, 1);
            ps += __shfl_xor_sync(0xffffffffu, ps, 2);
            pd += __shfl_xor_sync(0xffffffffu, pd, 1);
            pd += __shfl_xor_sync(0xffffffffu, pd, 2);
            int rl = wm * 32 + mf * 16 + h * 8 + g;
            if (tg == 0) {
                fS[rl * 2 + wn] = ps;
                fD[rl * 2 + wn] = pd;
            }
            if (r < nrows) {
                float* o = OutBuf + (size_t)r * 64 + wn * 32 + tg * 2;
#pragma unroll
                for (int nf = 0; nf < 4; nf++)
                    *(float2*)(o + nf * 8) = make_float2(acc[mf][nf][h * 2], acc[mf][nf][h * 2 + 1]);
            }
        }
    }
    __syncthreads();
    if (t < 128 && row0 + t < nrows) {
        g_as[row0 + t] = fS[t * 2] + fS[t * 2 + 1];
        g_ad[row0 + t] = fD[t * 2] + fD[t * 2 + 1];
    }
}

// ---------------- fused edge-softmax + aggregation (unroll-2, proven) ----------------
template <int HB, int OB>
__global__ void __launch_bounds__(256) agg_kernel(const float* __restrict__ bias, int N) {
    constexpr int CAP = 128;
    __shared__ float ce[8][CAP];
    __shared__ int   cs[8][CAP];
    const float* H = bufsel(HB);
    float* Out = bufsel(OB);

    int wl = threadIdx.x >> 5;
    int lane = threadIdx.x & 31;
    int d = blockIdx.x * 8 + wl;
    if (d >= N) return;

    int beg = g_rowstart[d], end = g_rowstart[d + 1];
    int deg = end - beg;
    float ad = g_ad[d];

    float mx = -3.4e38f;
    for (int j = lane; j < deg; j += 32) {
        int s = g_srcsorted[beg + j];
        float e = g_as[s] + ad;
        e = (e >= 0.f) ? e : NEG_SLOPE * e;
        if (j < CAP) { ce[wl][j] = e; cs[wl][j] = s; }
        mx = fmaxf(mx, e);
    }
#pragma unroll
    for (int o = 16; o; o >>= 1) mx = fmaxf(mx, __shfl_xor_sync(0xffffffffu, mx, o));

    float sum = 0.f;
    for (int j = lane; j < deg; j += 32) {
        float e;
        if (j < CAP) e = ce[wl][j];
        else {
            int s = g_srcsorted[beg + j];
            e = g_as[s] + ad;
            e = (e >= 0.f) ? e : NEG_SLOPE * e;
        }
        float w = __expf(e - mx);
        if (j < CAP) ce[wl][j] = w;
        sum += w;
    }
#pragma unroll
    for (int o = 16; o; o >>= 1) sum += __shfl_xor_sync(0xffffffffu, sum, o);
    float inv = 1.0f / sum;
    __syncwarp();

    float a0 = 0.f, a1 = 0.f, c0 = 0.f, c1 = 0.f;
    int j = 0;
    for (; j + 2 <= deg; j += 2) {
        float w0, w1; int s0, s1;
        if (j < CAP) { w0 = ce[wl][j]; s0 = cs[wl][j]; }
        else {
            s0 = g_srcsorted[beg + j];
            float e = g_as[s0] + ad; e = (e >= 0.f) ? e : NEG_SLOPE * e;
            w0 = __expf(e - mx);
        }
        if (j + 1 < CAP) { w1 = ce[wl][j + 1]; s1 = cs[wl][j + 1]; }
        else {
            s1 = g_srcsorted[beg + j + 1];
            float e = g_as[s1] + ad; e = (e >= 0.f) ? e : NEG_SLOPE * e;
            w1 = __expf(e - mx);
        }
        float2 h0 = ((const float2*)H)[(size_t)s0 * 32 + lane];
        float2 h1 = ((const float2*)H)[(size_t)s1 * 32 + lane];
        float al0 = w0 * inv, al1 = w1 * inv;
        a0 += al0 * h0.x; a1 += al0 * h0.y;
        c0 += al1 * h1.x; c1 += al1 * h1.y;
    }
    if (j < deg) {
        float w; int s;
        if (j < CAP) { w = ce[wl][j]; s = cs[wl][j]; }
        else {
            s = g_srcsorted[beg + j];
            float e = g_as[s] + ad; e = (e >= 0.f) ? e : NEG_SLOPE * e;
            w = __expf(e - mx);
        }
        float alpha = w * inv;
        float2 hv = ((const float2*)H)[(size_t)s * 32 + lane];
        a0 += alpha * hv.x; a1 += alpha * hv.y;
    }
    a0 += c0; a1 += c1;

    float2 b = ((const float2*)bias)[lane];
    a0 = fmaxf(a0 + b.x, 0.f);
    a1 = fmaxf(a1 + b.y, 0.f);
    ((float2*)Out)[(size_t)d * 32 + lane] = make_float2(a0, a1);
}

// ---------------- mean pool per graph + final linear [64 x 2] ----------------
template <int HB>
__global__ void pool_kernel(const void* __restrict__ batch,
                            const float* __restrict__ Wlin,
                            const float* __restrict__ blin,
                            float* __restrict__ out, int N) {
    __shared__ float pooled[64];
    __shared__ int sb, se;
    const float* H = bufsel(HB);
    int g = blockIdx.x;
    if (threadIdx.x == 0) {
        int is64 = g_idx64;
        int lo = 0, hi = N;
        while (lo < hi) { int mid = (lo + hi) >> 1; if (loadIdx(batch, mid, is64) < g) lo = mid + 1; else hi = mid; }
        sb = lo;
        hi = N;
        while (lo < hi) { int mid = (lo + hi) >> 1; if (loadIdx(batch, mid, is64) < g + 1) lo = mid + 1; else hi = mid; }
        se = lo;
    }
    __syncthreads();
    int c = threadIdx.x;
    float acc = 0.f;
    int b0 = sb, b1 = se;
    for (int i = b0; i < b1; i++) acc += H[(size_t)i * 64 + c];
    float cnt = (float)max(b1 - b0, 1);
    pooled[c] = acc / cnt;
    __syncthreads();
    if (c < 2) {
        float o = blin[c];
#pragma unroll
        for (int k = 0; k < 64; k++) o += pooled[k] * Wlin[k * 2 + c];
        out[g * 2 + c] = o;
    }
}

// ---------------- launch ----------------
extern "C" void kernel_launch(void* const* d_in, const int* in_sizes, int n_in,
                              void* d_out, int out_size) {
    const float* x    = (const float*)d_in[0];
    const void*  ei   = d_in[1];
    const void*  batch= d_in[2];
    const float* W1   = (const float*)d_in[3];
    const float* as1  = (const float*)d_in[4];
    const float* ad1  = (const float*)d_in[5];
    const float* b1   = (const float*)d_in[6];
    const float* W2   = (const float*)d_in[7];
    const float* as2  = (const float*)d_in[8];
    const float* ad2  = (const float*)d_in[9];
    const float* b2   = (const float*)d_in[10];
    const float* Wlin = (const float*)d_in[11];
    const float* blin = (const float*)d_in[12];
    float* out = (float*)d_out;

    int N = in_sizes[2];
    int E = in_sizes[1] / 2;
    if (N > NMAX) N = NMAX;
    if (E + N > ETOTMAX) E = ETOTMAX - N;
    int G = out_size / 2;
    int tot = E + N;
    int nb = (N + SCANBLK - 1) / SCANBLK;

    int gemmBlocks = (N + 127) / 128;
    int aggBlocks  = (N + 7) / 8;

    cudaFuncSetAttribute(gemm_mma_kernel<12, -1, 0, 1>, cudaFuncAttributeMaxDynamicSharedMemorySize, G1SMEM);
    cudaFuncSetAttribute(gemm_mma_kernel<1, 1, 0, 2>, cudaFuncAttributeMaxDynamicSharedMemorySize, G1SMEM);

    // fork a second stream so CSR build overlaps gemm1 path
    cudaStream_t sB;
    cudaStreamCreateWithFlags(&sB, cudaStreamNonBlocking);
    cudaEvent_t eF, eJ;
    cudaEventCreateWithFlags(&eF, cudaEventDisableTiming);
    cudaEventCreateWithFlags(&eJ, cudaEventDisableTiming);
    cudaEventRecord(eF, 0);
    cudaStreamWaitEvent(sB, eF, 0);

    // ---- branch A (default stream): CSR build ----
    zero_detect_kernel<<<(N + 255) / 256, 256>>>(batch, N);
    hist_kernel<<<(tot + 255) / 256, 256>>>(ei, E, N);
    partial_scan_kernel<<<nb, SCANBLK>>>(N);
    scan_sums_kernel<<<1, 1024>>>(nb);
    add_off_kernel<<<(N + 255) / 256, 256>>>(N, tot);
    scatter_kernel<<<(tot + 255) / 256, 256>>>(ei, E, N);

    // ---- branch B (sB): fused weight prep + gemm1 (+ att1 fused) ----
    wprep_both_kernel<<<(W1ELEMS + W2ELEMS + 255) / 256, 256, 0, sB>>>(W1, W2);
    gemm_mma_kernel<12, -1, 0, 1><<<gemmBlocks, 256, G1SMEM, sB>>>(x, as1, ad1, N);

    // ---- join ----
    cudaEventRecord(eJ, sB);
    cudaStreamWaitEvent(0, eJ, 0);

    // layer 1 aggregate, then layer 2 (+ att2 fused), then pool
    agg_kernel<0, 1><<<aggBlocks, 256>>>(b1, N);
    gemm_mma_kernel<1, 1, 0, 2><<<gemmBlocks, 256, G1SMEM>>>(nullptr, as2, ad2, N);
    agg_kernel<0, 1><<<aggBlocks, 256>>>(b2, N);
    pool_kernel<1><<<G, 64>>>(batch, Wlin, blin, out, N);

    cudaEventDestroy(eF);
    cudaEventDestroy(eJ);
    cudaStreamDestroy(sB);
}

// round 11
// speedup vs baseline: 1.0709x; 1.0709x over previous
#include <cuda_runtime.h>
#include <cuda_bf16.h>
#include <math.h>

#define NEG_SLOPE 0.2f

// ---------------- device scratch (no allocations allowed) ----------------
#define NMAX 50000
#define ETOTMAX 850000
#define SCANBLK 256
#define MAXSB 1024

__device__ float g_bufA[NMAX * 64];
__device__ float g_bufB[NMAX * 64];
__device__ float g_as[NMAX];
__device__ float g_ad[NMAX];
__device__ int   g_count[NMAX];
__device__ int   g_rowstart[NMAX + 1];
__device__ int   g_cursor[NMAX];
__device__ int   g_srcsorted[ETOTMAX];
__device__ int   g_blocksum[MAXSB];
__device__ int   g_blockoff[MAXSB];
__device__ int   g_idx64;
__device__ __nv_bfloat16 g_w1hi[64 * 768];
__device__ __nv_bfloat16 g_w1lo[64 * 768];
__device__ __nv_bfloat16 g_w2hi[64 * 64];
__device__ __nv_bfloat16 g_w2lo[64 * 64];

__device__ __forceinline__ float* bufsel(int id) { return id == 0 ? g_bufA : g_bufB; }

__device__ __forceinline__ int loadIdx(const void* p, long long i, int is64) {
    if (is64) return (int)((const long long*)p)[i];
    return ((const int*)p)[i];
}

// packed f32x2 -> bf16x2 (first arg lands in upper 16 bits, second in lower)
__device__ __forceinline__ unsigned cvt2bf(float hi, float lo) {
    unsigned r;
    asm("cvt.rn.bf16x2.f32 %0, %1, %2;" : "=r"(r) : "f"(hi), "f"(lo));
    return r;
}
__device__ __forceinline__ float bf_lo_as_f32(unsigned p) { return __uint_as_float(p << 16); }
__device__ __forceinline__ float bf_hi_as_f32(unsigned p) { return __uint_as_float(p & 0xFFFF0000u); }

// bf16 tensor-core MMA (sm_80+ path; compiles under compute_103)
__device__ __forceinline__ void mma_bf16(float* c, const unsigned* a, const unsigned* b) {
    asm volatile(
        "mma.sync.aligned.m16n8k16.row.col.f32.bf16.bf16.f32 "
        "{%0,%1,%2,%3}, {%4,%5,%6,%7}, {%8,%9}, {%0,%1,%2,%3};"
        : "+f"(c[0]), "+f"(c[1]), "+f"(c[2]), "+f"(c[3])
        : "r"(a[0]), "r"(a[1]), "r"(a[2]), "r"(a[3]), "r"(b[0]), "r"(b[1]));
}

// ---------------- zero counts + dtype probe (fused) ----------------
__global__ void zero_detect_kernel(const void* __restrict__ batch, int N) {
    int i = blockIdx.x * blockDim.x + threadIdx.x;
    if (i < N) g_count[i] = 0;
    if (blockIdx.x == 0) {
        __shared__ int nz;
        if (threadIdx.x == 0) nz = 0;
        __syncthreads();
        const int* w = (const int*)batch;
        int local = 0;
        for (int j = 1 + 2 * threadIdx.x; j < N; j += 2 * blockDim.x)
            if (w[j] != 0) local = 1;
        if (local) atomicOr(&nz, 1);
        __syncthreads();
        if (threadIdx.x == 0) g_idx64 = (nz == 0) ? 1 : 0;
    }
}

// ---------------- graph build ----------------
__global__ void hist_kernel(const void* __restrict__ ei, int E, int N) {
    int i = blockIdx.x * blockDim.x + threadIdx.x;
    int tot = E + N;
    if (i >= tot) return;
    int is64 = g_idx64;
    int dst = (i < E) ? loadIdx(ei, (long long)E + i, is64) : (i - E);
    atomicAdd(&g_count[dst], 1);
}

__global__ void partial_scan_kernel(int N) {
    __shared__ int wsum[8];
    int t = threadIdx.x;
    int idx = blockIdx.x * SCANBLK + t;
    int v = (idx < N) ? g_count[idx] : 0;
    int lane = t & 31, w = t >> 5;
    int s = v;
#pragma unroll
    for (int o = 1; o < 32; o <<= 1) {
        int u = __shfl_up_sync(0xffffffffu, s, o);
        if (lane >= o) s += u;
    }
    if (lane == 31) wsum[w] = s;
    __syncthreads();
    if (w == 0) {
        int ws = (lane < 8) ? wsum[lane] : 0;
#pragma unroll
        for (int o = 1; o < 8; o <<= 1) {
            int u = __shfl_up_sync(0xffffffffu, ws, o);
            if (lane >= o) ws += u;
        }
        if (lane < 8) wsum[lane] = ws;
    }
    __syncthreads();
    int incl = s + (w > 0 ? wsum[w - 1] : 0);
    if (idx < N) g_rowstart[idx] = incl - v;
    if (t == SCANBLK - 1) g_blocksum[blockIdx.x] = incl;
}

__global__ void scan_sums_kernel(int nb) {
    __shared__ int wsum[32];
    int t = threadIdx.x;
    int lane = t & 31, w = t >> 5;
    int v = (t < nb) ? g_blocksum[t] : 0;
    int s = v;
#pragma unroll
    for (int o = 1; o < 32; o <<= 1) {
        int u = __shfl_up_sync(0xffffffffu, s, o);
        if (lane >= o) s += u;
    }
    if (lane == 31) wsum[w] = s;
    __syncthreads();
    if (w == 0) {
        int ws = wsum[lane];
#pragma unroll
        for (int o = 1; o < 32; o <<= 1) {
            int u = __shfl_up_sync(0xffffffffu, ws, o);
            if (lane >= o) ws += u;
        }
        wsum[lane] = ws;
    }
    __syncthreads();
    int excl = s - v + (w > 0 ? wsum[w - 1] : 0);
    if (t < nb) g_blockoff[t] = excl;
}

__global__ void add_off_kernel(int N, int tot) {
    int idx = blockIdx.x * blockDim.x + threadIdx.x;
    if (idx < N) {
        int r = g_rowstart[idx] + g_blockoff[idx >> 8];
        g_rowstart[idx] = r;
        g_cursor[idx] = r;
    }
    if (idx == 0) g_rowstart[N] = tot;
}

__global__ void scatter_kernel(const void* __restrict__ ei, int E, int N) {
    int i = blockIdx.x * blockDim.x + threadIdx.x;
    int tot = E + N;
    if (i >= tot) return;
    int is64 = g_idx64;
    int src, dst;
    if (i < E) {
        src = loadIdx(ei, i, is64);
        dst = loadIdx(ei, (long long)E + i, is64);
    } else {
        src = i - E; dst = i - E;
    }
    int pos = atomicAdd(&g_cursor[dst], 1);
    g_srcsorted[pos] = src;
}

// ---------------- W prep (fused W1+W2): transpose + bf16 hi/lo split ----------------
#define W1ELEMS (768 * 64)
#define W2ELEMS (64 * 64)
__global__ void wprep_both_kernel(const float* __restrict__ W1, const float* __restrict__ W2) {
    int t = blockIdx.x * blockDim.x + threadIdx.x;
    if (t < W1ELEMS) {
        int k = t >> 6, n = t & 63;
        float v = W1[t];
        __nv_bfloat16 hi = __float2bfloat16(v);
        __nv_bfloat16 lo = __float2bfloat16(v - __bfloat162float(hi));
        g_w1hi[n * 768 + k] = hi;
        g_w1lo[n * 768 + k] = lo;
    } else if (t < W1ELEMS + W2ELEMS) {
        int u = t - W1ELEMS;
        int k = u >> 6, n = u & 63;
        float v = W2[u];
        __nv_bfloat16 hi = __float2bfloat16(v);
        __nv_bfloat16 lo = __float2bfloat16(v - __bfloat162float(hi));
        g_w2hi[n * 64 + k] = hi;
        g_w2lo[n * 64 + k] = lo;
    }
}

// ---------------- GEMM via mma.sync bf16x3 + fused attention scores ----------------
// H[N,64] = X[N,NKC*64] @ W; also writes g_as = H@att_s, g_ad = H@att_d.
// 256 threads, 8 warps as 4(m) x 2(n); block tile 128x64; K chunks of 64.
// occ 2, X+W register prefetch (round-9 proven configuration).
#define ASTR 144
#define G1SMEM (2 * 128 * ASTR + 2 * 64 * ASTR)   // 55296 B

template <int NKC, int XB, int DB, int WSel>
__global__ void __launch_bounds__(256, 2) gemm_mma_kernel(const float* __restrict__ Xext,
                                                          const float* __restrict__ att_s,
                                                          const float* __restrict__ att_d,
                                                          int nrows) {
    extern __shared__ char sm[];
    char* sAh = sm;
    char* sAl = sm + 128 * ASTR;
    char* sBh = sm + 2 * 128 * ASTR;
    char* sBl = sBh + 64 * ASTR;

    const int t = threadIdx.x;
    const int lane = t & 31, wid = t >> 5;
    const int g = lane >> 2, tg = lane & 3;
    const int wm = wid >> 1, wn = wid & 1;
    const int row0 = blockIdx.x * 128;

    const float* X = (XB < 0) ? Xext : bufsel(XB);
    float* OutBuf = bufsel(DB);
    const float4* X4 = (const float4*)X;
    const uint2* WH = (const uint2*)((WSel == 1) ? g_w1hi : g_w2hi);
    const uint2* WL = (const uint2*)((WSel == 1) ? g_w1lo : g_w2lo);

    float acc[2][4][4];
#pragma unroll
    for (int a = 0; a < 2; a++)
#pragma unroll
        for (int b = 0; b < 4; b++)
#pragma unroll
            for (int c = 0; c < 4; c++) acc[a][b][c] = 0.f;

    float4 px[8];
    uint2 pwh[4], pwl[4];

    auto loadX = [&](int kc) {
#pragma unroll
        for (int i = 0; i < 8; i++) {
            int idx = t + i * 256, r = idx >> 4, q = idx & 15;
            px[i] = (row0 + r < nrows) ? X4[(size_t)(row0 + r) * (NKC * 16) + kc * 16 + q]
                                       : make_float4(0.f, 0.f, 0.f, 0.f);
        }
    };
    auto loadW = [&](int kc) {
#pragma unroll
        for (int i = 0; i < 4; i++) {
            int idx = t + i * 256, n = idx >> 4, q = idx & 15;
            pwh[i] = WH[n * (NKC * 16) + kc * 16 + q];
            pwl[i] = WL[n * (NKC * 16) + kc * 16 + q];
        }
    };
    auto stage = [&]() {
#pragma unroll
        for (int i = 0; i < 8; i++) {
            int idx = t + i * 256, r = idx >> 4, q = idx & 15;
            float4 v = px[i];
            unsigned h01 = cvt2bf(v.y, v.x);
            unsigned h23 = cvt2bf(v.w, v.z);
            float l0 = v.x - bf_lo_as_f32(h01);
            float l1 = v.y - bf_hi_as_f32(h01);
            float l2 = v.z - bf_lo_as_f32(h23);
            float l3 = v.w - bf_hi_as_f32(h23);
            unsigned l01 = cvt2bf(l1, l0);
            unsigned l23 = cvt2bf(l3, l2);
            *(uint2*)(sAh + r * ASTR + q * 8) = make_uint2(h01, h23);
            *(uint2*)(sAl + r * ASTR + q * 8) = make_uint2(l01, l23);
        }
#pragma unroll
        for (int i = 0; i < 4; i++) {
            int idx = t + i * 256, n = idx >> 4, q = idx & 15;
            *(uint2*)(sBh + n * ASTR + q * 8) = pwh[i];
            *(uint2*)(sBl + n * ASTR + q * 8) = pwl[i];
        }
    };

    loadX(0); loadW(0);
    for (int kc = 0; kc < NKC; kc++) {
        stage();
        __syncthreads();
        if (kc < NKC - 1) { loadX(kc + 1); loadW(kc + 1); }
#pragma unroll
        for (int ks = 0; ks < 4; ks++) {
            unsigned ah[2][4], al[2][4];
#pragma unroll
            for (int mf = 0; mf < 2; mf++) {
                int roff = (wm * 32 + mf * 16 + g) * ASTR + ks * 32 + tg * 4;
                ah[mf][0] = *(const unsigned*)(sAh + roff);
                ah[mf][1] = *(const unsigned*)(sAh + roff + 8 * ASTR);
                ah[mf][2] = *(const unsigned*)(sAh + roff + 16);
                ah[mf][3] = *(const unsigned*)(sAh + roff + 8 * ASTR + 16);
                al[mf][0] = *(const unsigned*)(sAl + roff);
                al[mf][1] = *(const unsigned*)(sAl + roff + 8 * ASTR);
                al[mf][2] = *(const unsigned*)(sAl + roff + 16);
                al[mf][3] = *(const unsigned*)(sAl + roff + 8 * ASTR + 16);
            }
#pragma unroll
            for (int nf = 0; nf < 4; nf++) {
                int noff = (wn * 32 + nf * 8 + g) * ASTR + ks * 32 + tg * 4;
                unsigned bh[2], bl[2];
                bh[0] = *(const unsigned*)(sBh + noff);
                bh[1] = *(const unsigned*)(sBh + noff + 16);
                bl[0] = *(const unsigned*)(sBl + noff);
                bl[1] = *(const unsigned*)(sBl + noff + 16);
#pragma unroll
                for (int mf = 0; mf < 2; mf++) {
                    mma_bf16(acc[mf][nf], ah[mf], bh);
                    mma_bf16(acc[mf][nf], ah[mf], bl);
                    mma_bf16(acc[mf][nf], al[mf], bh);
                }
            }
        }
        __syncthreads();
    }

    // ---- epilogue: store D + fused attention scores ----
    float asc[8], adc[8];
#pragma unroll
    for (int nf = 0; nf < 4; nf++) {
        int c = wn * 32 + nf * 8 + tg * 2;
        asc[nf * 2] = att_s[c]; asc[nf * 2 + 1] = att_s[c + 1];
        adc[nf * 2] = att_d[c]; adc[nf * 2 + 1] = att_d[c + 1];
    }
    float* fS = (float*)sm;          // [128][2]
    float* fD = (float*)sm + 256;    // [128][2]

#pragma unroll
    for (int mf = 0; mf < 2; mf++) {
        int rbase = row0 + wm * 32 + mf * 16;
#pragma unroll
        for (int h = 0; h < 2; h++) {
            int r = rbase + g + h * 8;
            float ps = 0.f, pd = 0.f;
#pragma unroll
            for (int nf = 0; nf < 4; nf++) {
                float v0 = acc[mf][nf][h * 2], v1 = acc[mf][nf][h * 2 + 1];
                ps += v0 * asc[nf * 2] + v1 * asc[nf * 2 + 1];
                pd += v0 * adc[nf * 2] + v1 * adc[nf * 2 + 1];
            }
            ps += __shfl_xor_sync(0xffffffffu, ps, 1);
            ps += __shfl_xor_sync(0xffffffffu, ps, 2);
            pd += __shfl_xor_sync(0xffffffffu, pd, 1);
            pd += __shfl_xor_sync(0xffffffffu, pd, 2);
            int rl = wm * 32 + mf * 16 + h * 8 + g;
            if (tg == 0) {
                fS[rl * 2 + wn] = ps;
                fD[rl * 2 + wn] = pd;
            }
            if (r < nrows) {
                float* o = OutBuf + (size_t)r * 64 + wn * 32 + tg * 2;
#pragma unroll
                for (int nf = 0; nf < 4; nf++)
                    *(float2*)(o + nf * 8) = make_float2(acc[mf][nf][h * 2], acc[mf][nf][h * 2 + 1]);
            }
        }
    }
    __syncthreads();
    if (t < 128 && row0 + t < nrows) {
        g_as[row0 + t] = fS[t * 2] + fS[t * 2 + 1];
        g_ad[row0 + t] = fD[t * 2] + fD[t * 2 + 1];
    }
}

// ---------------- fused edge-softmax + aggregation (unroll-2, proven) ----------------
template <int HB, int OB>
__global__ void __launch_bounds__(256) agg_kernel(const float* __restrict__ bias, int N) {
    constexpr int CAP = 128;
    __shared__ float ce[8][CAP];
    __shared__ int   cs[8][CAP];
    const float* H = bufsel(HB);
    float* Out = bufsel(OB);

    int wl = threadIdx.x >> 5;
    int lane = threadIdx.x & 31;
    int d = blockIdx.x * 8 + wl;
    if (d >= N) return;

    int beg = g_rowstart[d], end = g_rowstart[d + 1];
    int deg = end - beg;
    float ad = g_ad[d];

    float mx = -3.4e38f;
    for (int j = lane; j < deg; j += 32) {
        int s = g_srcsorted[beg + j];
        float e = g_as[s] + ad;
        e = (e >= 0.f) ? e : NEG_SLOPE * e;
        if (j < CAP) { ce[wl][j] = e; cs[wl][j] = s; }
        mx = fmaxf(mx, e);
    }
#pragma unroll
    for (int o = 16; o; o >>= 1) mx = fmaxf(mx, __shfl_xor_sync(0xffffffffu, mx, o));

    float sum = 0.f;
    for (int j = lane; j < deg; j += 32) {
        float e;
        if (j < CAP) e = ce[wl][j];
        else {
            int s = g_srcsorted[beg + j];
            e = g_as[s] + ad;
            e = (e >= 0.f) ? e : NEG_SLOPE * e;
        }
        float w = __expf(e - mx);
        if (j < CAP) ce[wl][j] = w;
        sum += w;
    }
#pragma unroll
    for (int o = 16; o; o >>= 1) sum += __shfl_xor_sync(0xffffffffu, sum, o);
    float inv = 1.0f / sum;
    __syncwarp();

    float a0 = 0.f, a1 = 0.f, c0 = 0.f, c1 = 0.f;
    int j = 0;
    for (; j + 2 <= deg; j += 2) {
        float w0, w1; int s0, s1;
        if (j < CAP) { w0 = ce[wl][j]; s0 = cs[wl][j]; }
        else {
            s0 = g_srcsorted[beg + j];
            float e = g_as[s0] + ad; e = (e >= 0.f) ? e : NEG_SLOPE * e;
            w0 = __expf(e - mx);
        }
        if (j + 1 < CAP) { w1 = ce[wl][j + 1]; s1 = cs[wl][j + 1]; }
        else {
            s1 = g_srcsorted[beg + j + 1];
            float e = g_as[s1] + ad; e = (e >= 0.f) ? e : NEG_SLOPE * e;
            w1 = __expf(e - mx);
        }
        float2 h0 = ((const float2*)H)[(size_t)s0 * 32 + lane];
        float2 h1 = ((const float2*)H)[(size_t)s1 * 32 + lane];
        float al0 = w0 * inv, al1 = w1 * inv;
        a0 += al0 * h0.x; a1 += al0 * h0.y;
        c0 += al1 * h1.x; c1 += al1 * h1.y;
    }
    if (j < deg) {
        float w; int s;
        if (j < CAP) { w = ce[wl][j]; s = cs[wl][j]; }
        else {
            s = g_srcsorted[beg + j];
            float e = g_as[s] + ad; e = (e >= 0.f) ? e : NEG_SLOPE * e;
            w = __expf(e - mx);
        }
        float alpha = w * inv;
        float2 hv = ((const float2*)H)[(size_t)s * 32 + lane];
        a0 += alpha * hv.x; a1 += alpha * hv.y;
    }
    a0 += c0; a1 += c1;

    float2 b = ((const float2*)bias)[lane];
    a0 = fmaxf(a0 + b.x, 0.f);
    a1 = fmaxf(a1 + b.y, 0.f);
    ((float2*)Out)[(size_t)d * 32 + lane] = make_float2(a0, a1);
}

// ---------------- mean pool per graph + final linear [64 x 2] ----------------
template <int HB>
__global__ void pool_kernel(const void* __restrict__ batch,
                            const float* __restrict__ Wlin,
                            const float* __restrict__ blin,
                            float* __restrict__ out, int N) {
    __shared__ float pooled[64];
    __shared__ int sb, se;
    const float* H = bufsel(HB);
    int g = blockIdx.x;
    if (threadIdx.x == 0) {
        int is64 = g_idx64;
        int lo = 0, hi = N;
        while (lo < hi) { int mid = (lo + hi) >> 1; if (loadIdx(batch, mid, is64) < g) lo = mid + 1; else hi = mid; }
        sb = lo;
        hi = N;
        while (lo < hi) { int mid = (lo + hi) >> 1; if (loadIdx(batch, mid, is64) < g + 1) lo = mid + 1; else hi = mid; }
        se = lo;
    }
    __syncthreads();
    int c = threadIdx.x;
    float acc = 0.f;
    int b0 = sb, b1 = se;
    for (int i = b0; i < b1; i++) acc += H[(size_t)i * 64 + c];
    float cnt = (float)max(b1 - b0, 1);
    pooled[c] = acc / cnt;
    __syncthreads();
    if (c < 2) {
        float o = blin[c];
#pragma unroll
        for (int k = 0; k < 64; k++) o += pooled[k] * Wlin[k * 2 + c];
        out[g * 2 + c] = o;
    }
}

// ---------------- launch ----------------
extern "C" void kernel_launch(void* const* d_in, const int* in_sizes, int n_in,
                              void* d_out, int out_size) {
    const float* x    = (const float*)d_in[0];
    const void*  ei   = d_in[1];
    const void*  batch= d_in[2];
    const float* W1   = (const float*)d_in[3];
    const float* as1  = (const float*)d_in[4];
    const float* ad1  = (const float*)d_in[5];
    const float* b1   = (const float*)d_in[6];
    const float* W2   = (const float*)d_in[7];
    const float* as2  = (const float*)d_in[8];
    const float* ad2  = (const float*)d_in[9];
    const float* b2   = (const float*)d_in[10];
    const float* Wlin = (const float*)d_in[11];
    const float* blin = (const float*)d_in[12];
    float* out = (float*)d_out;

    int N = in_sizes[2];
    int E = in_sizes[1] / 2;
    if (N > NMAX) N = NMAX;
    if (E + N > ETOTMAX) E = ETOTMAX - N;
    int G = out_size / 2;
    int tot = E + N;
    int nb = (N + SCANBLK - 1) / SCANBLK;

    int gemmBlocks = (N + 127) / 128;
    int aggBlocks  = (N + 7) / 8;

    cudaFuncSetAttribute(gemm_mma_kernel<12, -1, 0, 1>, cudaFuncAttributeMaxDynamicSharedMemorySize, G1SMEM);
    cudaFuncSetAttribute(gemm_mma_kernel<1, 1, 0, 2>, cudaFuncAttributeMaxDynamicSharedMemorySize, G1SMEM);

    // fork a second stream so CSR build overlaps gemm1 path
    cudaStream_t sB;
    cudaStreamCreateWithFlags(&sB, cudaStreamNonBlocking);
    cudaEvent_t eF, eJ;
    cudaEventCreateWithFlags(&eF, cudaEventDisableTiming);
    cudaEventCreateWithFlags(&eJ, cudaEventDisableTiming);
    cudaEventRecord(eF, 0);
    cudaStreamWaitEvent(sB, eF, 0);

    // ---- branch A (default stream): CSR build ----
    zero_detect_kernel<<<(N + 255) / 256, 256>>>(batch, N);
    hist_kernel<<<(tot + 255) / 256, 256>>>(ei, E, N);
    partial_scan_kernel<<<nb, SCANBLK>>>(N);
    scan_sums_kernel<<<1, 1024>>>(nb);
    add_off_kernel<<<(N + 255) / 256, 256>>>(N, tot);
    scatter_kernel<<<(tot + 255) / 256, 256>>>(ei, E, N);

    // ---- branch B (sB): fused weight prep + gemm1 (+ att1 fused) ----
    wprep_both_kernel<<<(W1ELEMS + W2ELEMS + 255) / 256, 256, 0, sB>>>(W1, W2);
    gemm_mma_kernel<12, -1, 0, 1><<<gemmBlocks, 256, G1SMEM, sB>>>(x, as1, ad1, N);

    // ---- join ----
    cudaEventRecord(eJ, sB);
    cudaStreamWaitEvent(0, eJ, 0);

    // layer 1 aggregate, then layer 2 (+ att2 fused), then pool
    agg_kernel<0, 1><<<aggBlocks, 256>>>(b1, N);
    gemm_mma_kernel<1, 1, 0, 2><<<gemmBlocks, 256, G1SMEM>>>(nullptr, as2, ad2, N);
    agg_kernel<0, 1><<<aggBlocks, 256>>>(b2, N);
    pool_kernel<1><<<G, 64>>>(batch, Wlin, blin, out, N);

    cudaEventDestroy(eF);
    cudaEventDestroy(eJ);
    cudaStreamDestroy(sB);
}

// round 12
// speedup vs baseline: 1.0839x; 1.0122x over previous
#include <cuda_runtime.h>
#include <cuda_bf16.h>
#include <math.h>

#define NEG_SLOPE 0.2f

// ---------------- device scratch (no allocations allowed) ----------------
#define NMAX 50000
#define ETOTMAX 850000
#define SCANBLK 256
#define MAXSB 1024

__device__ float g_bufA[NMAX * 64];
__device__ float g_bufB[NMAX * 64];
__device__ float g_as[NMAX];
__device__ float g_ad[NMAX];
__device__ int   g_count[NMAX];
__device__ int   g_rowstart[NMAX + 1];
__device__ int   g_cursor[NMAX];
__device__ int   g_srcsorted[ETOTMAX];
__device__ int   g_blocksum[MAXSB];
__device__ int   g_blockoff[MAXSB];
__device__ int   g_idx64;
__device__ __nv_bfloat16 g_w1hi[64 * 768];
__device__ __nv_bfloat16 g_w1lo[64 * 768];
__device__ __nv_bfloat16 g_w2hi[64 * 64];
__device__ __nv_bfloat16 g_w2lo[64 * 64];

__device__ __forceinline__ float* bufsel(int id) { return id == 0 ? g_bufA : g_bufB; }

__device__ __forceinline__ int loadIdx(const void* p, long long i, int is64) {
    if (is64) return (int)((const long long*)p)[i];
    return ((const int*)p)[i];
}

// packed f32x2 -> bf16x2 (first arg lands in upper 16 bits, second in lower)
__device__ __forceinline__ unsigned cvt2bf(float hi, float lo) {
    unsigned r;
    asm("cvt.rn.bf16x2.f32 %0, %1, %2;" : "=r"(r) : "f"(hi), "f"(lo));
    return r;
}
__device__ __forceinline__ float bf_lo_as_f32(unsigned p) { return __uint_as_float(p << 16); }
__device__ __forceinline__ float bf_hi_as_f32(unsigned p) { return __uint_as_float(p & 0xFFFF0000u); }

// bf16 tensor-core MMA (sm_80+ path; compiles under compute_103)
__device__ __forceinline__ void mma_bf16(float* c, const unsigned* a, const unsigned* b) {
    asm volatile(
        "mma.sync.aligned.m16n8k16.row.col.f32.bf16.bf16.f32 "
        "{%0,%1,%2,%3}, {%4,%5,%6,%7}, {%8,%9}, {%0,%1,%2,%3};"
        : "+f"(c[0]), "+f"(c[1]), "+f"(c[2]), "+f"(c[3])
        : "r"(a[0]), "r"(a[1]), "r"(a[2]), "r"(a[3]), "r"(b[0]), "r"(b[1]));
}

// ---------------- zero counts + dtype probe (fused) ----------------
__global__ void zero_detect_kernel(const void* __restrict__ batch, int N) {
    int i = blockIdx.x * blockDim.x + threadIdx.x;
    if (i < N) g_count[i] = 0;
    if (blockIdx.x == 0) {
        __shared__ int nz;
        if (threadIdx.x == 0) nz = 0;
        __syncthreads();
        const int* w = (const int*)batch;
        int local = 0;
        for (int j = 1 + 2 * threadIdx.x; j < N; j += 2 * blockDim.x)
            if (w[j] != 0) local = 1;
        if (local) atomicOr(&nz, 1);
        __syncthreads();
        if (threadIdx.x == 0) g_idx64 = (nz == 0) ? 1 : 0;
    }
}

// ---------------- graph build ----------------
__global__ void hist_kernel(const void* __restrict__ ei, int E, int N) {
    int i = blockIdx.x * blockDim.x + threadIdx.x;
    int tot = E + N;
    if (i >= tot) return;
    int is64 = g_idx64;
    int dst = (i < E) ? loadIdx(ei, (long long)E + i, is64) : (i - E);
    atomicAdd(&g_count[dst], 1);
}

__global__ void partial_scan_kernel(int N) {
    __shared__ int wsum[8];
    int t = threadIdx.x;
    int idx = blockIdx.x * SCANBLK + t;
    int v = (idx < N) ? g_count[idx] : 0;
    int lane = t & 31, w = t >> 5;
    int s = v;
#pragma unroll
    for (int o = 1; o < 32; o <<= 1) {
        int u = __shfl_up_sync(0xffffffffu, s, o);
        if (lane >= o) s += u;
    }
    if (lane == 31) wsum[w] = s;
    __syncthreads();
    if (w == 0) {
        int ws = (lane < 8) ? wsum[lane] : 0;
#pragma unroll
        for (int o = 1; o < 8; o <<= 1) {
            int u = __shfl_up_sync(0xffffffffu, ws, o);
            if (lane >= o) ws += u;
        }
        if (lane < 8) wsum[lane] = ws;
    }
    __syncthreads();
    int incl = s + (w > 0 ? wsum[w - 1] : 0);
    if (idx < N) g_rowstart[idx] = incl - v;
    if (t == SCANBLK - 1) g_blocksum[blockIdx.x] = incl;
}

__global__ void scan_sums_kernel(int nb) {
    __shared__ int wsum[32];
    int t = threadIdx.x;
    int lane = t & 31, w = t >> 5;
    int v = (t < nb) ? g_blocksum[t] : 0;
    int s = v;
#pragma unroll
    for (int o = 1; o < 32; o <<= 1) {
        int u = __shfl_up_sync(0xffffffffu, s, o);
        if (lane >= o) s += u;
    }
    if (lane == 31) wsum[w] = s;
    __syncthreads();
    if (w == 0) {
        int ws = wsum[lane];
#pragma unroll
        for (int o = 1; o < 32; o <<= 1) {
            int u = __shfl_up_sync(0xffffffffu, ws, o);
            if (lane >= o) ws += u;
        }
        wsum[lane] = ws;
    }
    __syncthreads();
    int excl = s - v + (w > 0 ? wsum[w - 1] : 0);
    if (t < nb) g_blockoff[t] = excl;
}

__global__ void add_off_kernel(int N, int tot) {
    int idx = blockIdx.x * blockDim.x + threadIdx.x;
    if (idx < N) {
        int r = g_rowstart[idx] + g_blockoff[idx >> 8];
        g_rowstart[idx] = r;
        g_cursor[idx] = r;
    }
    if (idx == 0) g_rowstart[N] = tot;
}

__global__ void scatter_kernel(const void* __restrict__ ei, int E, int N) {
    int i = blockIdx.x * blockDim.x + threadIdx.x;
    int tot = E + N;
    if (i >= tot) return;
    int is64 = g_idx64;
    int src, dst;
    if (i < E) {
        src = loadIdx(ei, i, is64);
        dst = loadIdx(ei, (long long)E + i, is64);
    } else {
        src = i - E; dst = i - E;
    }
    int pos = atomicAdd(&g_cursor[dst], 1);
    g_srcsorted[pos] = src;
}

// ---------------- W prep (fused W1+W2): transpose + bf16 hi/lo split ----------------
#define W1ELEMS (768 * 64)
#define W2ELEMS (64 * 64)
__global__ void wprep_both_kernel(const float* __restrict__ W1, const float* __restrict__ W2) {
    int t = blockIdx.x * blockDim.x + threadIdx.x;
    if (t < W1ELEMS) {
        int k = t >> 6, n = t & 63;
        float v = W1[t];
        __nv_bfloat16 hi = __float2bfloat16(v);
        __nv_bfloat16 lo = __float2bfloat16(v - __bfloat162float(hi));
        g_w1hi[n * 768 + k] = hi;
        g_w1lo[n * 768 + k] = lo;
    } else if (t < W1ELEMS + W2ELEMS) {
        int u = t - W1ELEMS;
        int k = u >> 6, n = u & 63;
        float v = W2[u];
        __nv_bfloat16 hi = __float2bfloat16(v);
        __nv_bfloat16 lo = __float2bfloat16(v - __bfloat162float(hi));
        g_w2hi[n * 64 + k] = hi;
        g_w2lo[n * 64 + k] = lo;
    }
}

// ---------------- GEMM via mma.sync bf16x3 + fused attention scores ----------------
// occ 2, X+W register prefetch (round-9 proven configuration).
#define ASTR 144
#define G1SMEM (2 * 128 * ASTR + 2 * 64 * ASTR)   // 55296 B

template <int NKC, int XB, int DB, int WSel>
__global__ void __launch_bounds__(256, 2) gemm_mma_kernel(const float* __restrict__ Xext,
                                                          const float* __restrict__ att_s,
                                                          const float* __restrict__ att_d,
                                                          int nrows) {
    extern __shared__ char sm[];
    char* sAh = sm;
    char* sAl = sm + 128 * ASTR;
    char* sBh = sm + 2 * 128 * ASTR;
    char* sBl = sBh + 64 * ASTR;

    const int t = threadIdx.x;
    const int lane = t & 31, wid = t >> 5;
    const int g = lane >> 2, tg = lane & 3;
    const int wm = wid >> 1, wn = wid & 1;
    const int row0 = blockIdx.x * 128;

    const float* X = (XB < 0) ? Xext : bufsel(XB);
    float* OutBuf = bufsel(DB);
    const float4* X4 = (const float4*)X;
    const uint2* WH = (const uint2*)((WSel == 1) ? g_w1hi : g_w2hi);
    const uint2* WL = (const uint2*)((WSel == 1) ? g_w1lo : g_w2lo);

    float acc[2][4][4];
#pragma unroll
    for (int a = 0; a < 2; a++)
#pragma unroll
        for (int b = 0; b < 4; b++)
#pragma unroll
            for (int c = 0; c < 4; c++) acc[a][b][c] = 0.f;

    float4 px[8];
    uint2 pwh[4], pwl[4];

    auto loadX = [&](int kc) {
#pragma unroll
        for (int i = 0; i < 8; i++) {
            int idx = t + i * 256, r = idx >> 4, q = idx & 15;
            px[i] = (row0 + r < nrows) ? X4[(size_t)(row0 + r) * (NKC * 16) + kc * 16 + q]
                                       : make_float4(0.f, 0.f, 0.f, 0.f);
        }
    };
    auto loadW = [&](int kc) {
#pragma unroll
        for (int i = 0; i < 4; i++) {
            int idx = t + i * 256, n = idx >> 4, q = idx & 15;
            pwh[i] = WH[n * (NKC * 16) + kc * 16 + q];
            pwl[i] = WL[n * (NKC * 16) + kc * 16 + q];
        }
    };
    auto stage = [&]() {
#pragma unroll
        for (int i = 0; i < 8; i++) {
            int idx = t + i * 256, r = idx >> 4, q = idx & 15;
            float4 v = px[i];
            unsigned h01 = cvt2bf(v.y, v.x);
            unsigned h23 = cvt2bf(v.w, v.z);
            float l0 = v.x - bf_lo_as_f32(h01);
            float l1 = v.y - bf_hi_as_f32(h01);
            float l2 = v.z - bf_lo_as_f32(h23);
            float l3 = v.w - bf_hi_as_f32(h23);
            unsigned l01 = cvt2bf(l1, l0);
            unsigned l23 = cvt2bf(l3, l2);
            *(uint2*)(sAh + r * ASTR + q * 8) = make_uint2(h01, h23);
            *(uint2*)(sAl + r * ASTR + q * 8) = make_uint2(l01, l23);
        }
#pragma unroll
        for (int i = 0; i < 4; i++) {
            int idx = t + i * 256, n = idx >> 4, q = idx & 15;
            *(uint2*)(sBh + n * ASTR + q * 8) = pwh[i];
            *(uint2*)(sBl + n * ASTR + q * 8) = pwl[i];
        }
    };

    loadX(0); loadW(0);
    for (int kc = 0; kc < NKC; kc++) {
        stage();
        __syncthreads();
        if (kc < NKC - 1) { loadX(kc + 1); loadW(kc + 1); }
#pragma unroll
        for (int ks = 0; ks < 4; ks++) {
            unsigned ah[2][4], al[2][4];
#pragma unroll
            for (int mf = 0; mf < 2; mf++) {
                int roff = (wm * 32 + mf * 16 + g) * ASTR + ks * 32 + tg * 4;
                ah[mf][0] = *(const unsigned*)(sAh + roff);
                ah[mf][1] = *(const unsigned*)(sAh + roff + 8 * ASTR);
                ah[mf][2] = *(const unsigned*)(sAh + roff + 16);
                ah[mf][3] = *(const unsigned*)(sAh + roff + 8 * ASTR + 16);
                al[mf][0] = *(const unsigned*)(sAl + roff);
                al[mf][1] = *(const unsigned*)(sAl + roff + 8 * ASTR);
                al[mf][2] = *(const unsigned*)(sAl + roff + 16);
                al[mf][3] = *(const unsigned*)(sAl + roff + 8 * ASTR + 16);
            }
#pragma unroll
            for (int nf = 0; nf < 4; nf++) {
                int noff = (wn * 32 + nf * 8 + g) * ASTR + ks * 32 + tg * 4;
                unsigned bh[2], bl[2];
                bh[0] = *(const unsigned*)(sBh + noff);
                bh[1] = *(const unsigned*)(sBh + noff + 16);
                bl[0] = *(const unsigned*)(sBl + noff);
                bl[1] = *(const unsigned*)(sBl + noff + 16);
#pragma unroll
                for (int mf = 0; mf < 2; mf++) {
                    mma_bf16(acc[mf][nf], ah[mf], bh);
                    mma_bf16(acc[mf][nf], ah[mf], bl);
                    mma_bf16(acc[mf][nf], al[mf], bh);
                }
            }
        }
        __syncthreads();
    }

    // ---- epilogue: store D + fused attention scores ----
    float asc[8], adc[8];
#pragma unroll
    for (int nf = 0; nf < 4; nf++) {
        int c = wn * 32 + nf * 8 + tg * 2;
        asc[nf * 2] = att_s[c]; asc[nf * 2 + 1] = att_s[c + 1];
        adc[nf * 2] = att_d[c]; adc[nf * 2 + 1] = att_d[c + 1];
    }
    float* fS = (float*)sm;          // [128][2]
    float* fD = (float*)sm + 256;    // [128][2]

#pragma unroll
    for (int mf = 0; mf < 2; mf++) {
        int rbase = row0 + wm * 32 + mf * 16;
#pragma unroll
        for (int h = 0; h < 2; h++) {
            int r = rbase + g + h * 8;
            float ps = 0.f, pd = 0.f;
#pragma unroll
            for (int nf = 0; nf < 4; nf++) {
                float v0 = acc[mf][nf][h * 2], v1 = acc[mf][nf][h * 2 + 1];
                ps += v0 * asc[nf * 2] + v1 * asc[nf * 2 + 1];
                pd += v0 * adc[nf * 2] + v1 * adc[nf * 2 + 1];
            }
            ps += __shfl_xor_sync(0xffffffffu, ps, 1);
            ps += __shfl_xor_sync(0xffffffffu, ps, 2);
            pd += __shfl_xor_sync(0xffffffffu, pd, 1);
            pd += __shfl_xor_sync(0xffffffffu, pd, 2);
            int rl = wm * 32 + mf * 16 + h * 8 + g;
            if (tg == 0) {
                fS[rl * 2 + wn] = ps;
                fD[rl * 2 + wn] = pd;
            }
            if (r < nrows) {
                float* o = OutBuf + (size_t)r * 64 + wn * 32 + tg * 2;
#pragma unroll
                for (int nf = 0; nf < 4; nf++)
                    *(float2*)(o + nf * 8) = make_float2(acc[mf][nf][h * 2], acc[mf][nf][h * 2 + 1]);
            }
        }
    }
    __syncthreads();
    if (t < 128 && row0 + t < nrows) {
        g_as[row0 + t] = fS[t * 2] + fS[t * 2 + 1];
        g_ad[row0 + t] = fD[t * 2] + fD[t * 2 + 1];
    }
}

// ---------------- fused edge-softmax + aggregation ----------------
// Fast path (deg<=32): one edge per lane, warp shuffles only, no smem.
// Slow path: proven smem unroll-2 code.
template <int HB, int OB>
__global__ void __launch_bounds__(256) agg_kernel(const float* __restrict__ bias, int N) {
    constexpr int CAP = 128;
    __shared__ float ce[8][CAP];
    __shared__ int   cs[8][CAP];
    const float* H = bufsel(HB);
    float* Out = bufsel(OB);

    int wl = threadIdx.x >> 5;
    int lane = threadIdx.x & 31;
    int d = blockIdx.x * 8 + wl;
    if (d >= N) return;

    int beg = g_rowstart[d], end = g_rowstart[d + 1];
    int deg = end - beg;
    float ad = g_ad[d];
    float2 b = ((const float2*)bias)[lane];

    if (deg <= 32) {
        // ---- register fast path ----
        int s = 0;
        float e = -3.4e38f;
        if (lane < deg) {
            s = g_srcsorted[beg + lane];
            e = g_as[s] + ad;
            e = (e >= 0.f) ? e : NEG_SLOPE * e;
        }
        float mx = e;
#pragma unroll
        for (int o = 16; o; o >>= 1) mx = fmaxf(mx, __shfl_xor_sync(0xffffffffu, mx, o));
        float w = (lane < deg) ? __expf(e - mx) : 0.f;
        float sum = w;
#pragma unroll
        for (int o = 16; o; o >>= 1) sum += __shfl_xor_sync(0xffffffffu, sum, o);
        float inv = 1.0f / sum;

        float a0 = 0.f, a1 = 0.f, c0 = 0.f, c1 = 0.f;
        int j = 0;
        for (; j + 2 <= deg; j += 2) {
            float w0 = __shfl_sync(0xffffffffu, w, j);
            int   s0 = __shfl_sync(0xffffffffu, s, j);
            float w1 = __shfl_sync(0xffffffffu, w, j + 1);
            int   s1 = __shfl_sync(0xffffffffu, s, j + 1);
            float2 h0 = ((const float2*)H)[(size_t)s0 * 32 + lane];
            float2 h1 = ((const float2*)H)[(size_t)s1 * 32 + lane];
            float al0 = w0 * inv, al1 = w1 * inv;
            a0 += al0 * h0.x; a1 += al0 * h0.y;
            c0 += al1 * h1.x; c1 += al1 * h1.y;
        }
        if (j < deg) {
            float w0 = __shfl_sync(0xffffffffu, w, j);
            int   s0 = __shfl_sync(0xffffffffu, s, j);
            float2 h0 = ((const float2*)H)[(size_t)s0 * 32 + lane];
            float al0 = w0 * inv;
            a0 += al0 * h0.x; a1 += al0 * h0.y;
        }
        a0 += c0; a1 += c1;
        a0 = fmaxf(a0 + b.x, 0.f);
        a1 = fmaxf(a1 + b.y, 0.f);
        ((float2*)Out)[(size_t)d * 32 + lane] = make_float2(a0, a1);
        return;
    }

    // ---- smem slow path (deg > 32) ----
    float mx = -3.4e38f;
    for (int j = lane; j < deg; j += 32) {
        int s = g_srcsorted[beg + j];
        float e = g_as[s] + ad;
        e = (e >= 0.f) ? e : NEG_SLOPE * e;
        if (j < CAP) { ce[wl][j] = e; cs[wl][j] = s; }
        mx = fmaxf(mx, e);
    }
#pragma unroll
    for (int o = 16; o; o >>= 1) mx = fmaxf(mx, __shfl_xor_sync(0xffffffffu, mx, o));

    float sum = 0.f;
    for (int j = lane; j < deg; j += 32) {
        float e;
        if (j < CAP) e = ce[wl][j];
        else {
            int s = g_srcsorted[beg + j];
            e = g_as[s] + ad;
            e = (e >= 0.f) ? e : NEG_SLOPE * e;
        }
        float w = __expf(e - mx);
        if (j < CAP) ce[wl][j] = w;
        sum += w;
    }
#pragma unroll
    for (int o = 16; o; o >>= 1) sum += __shfl_xor_sync(0xffffffffu, sum, o);
    float inv = 1.0f / sum;
    __syncwarp();

    float a0 = 0.f, a1 = 0.f, c0 = 0.f, c1 = 0.f;
    int j = 0;
    for (; j + 2 <= deg; j += 2) {
        float w0, w1; int s0, s1;
        if (j < CAP) { w0 = ce[wl][j]; s0 = cs[wl][j]; }
        else {
            s0 = g_srcsorted[beg + j];
            float e = g_as[s0] + ad; e = (e >= 0.f) ? e : NEG_SLOPE * e;
            w0 = __expf(e - mx);
        }
        if (j + 1 < CAP) { w1 = ce[wl][j + 1]; s1 = cs[wl][j + 1]; }
        else {
            s1 = g_srcsorted[beg + j + 1];
            float e = g_as[s1] + ad; e = (e >= 0.f) ? e : NEG_SLOPE * e;
            w1 = __expf(e - mx);
        }
        float2 h0 = ((const float2*)H)[(size_t)s0 * 32 + lane];
        float2 h1 = ((const float2*)H)[(size_t)s1 * 32 + lane];
        float al0 = w0 * inv, al1 = w1 * inv;
        a0 += al0 * h0.x; a1 += al0 * h0.y;
        c0 += al1 * h1.x; c1 += al1 * h1.y;
    }
    if (j < deg) {
        float w; int s;
        if (j < CAP) { w = ce[wl][j]; s = cs[wl][j]; }
        else {
            s = g_srcsorted[beg + j];
            float e = g_as[s] + ad; e = (e >= 0.f) ? e : NEG_SLOPE * e;
            w = __expf(e - mx);
        }
        float alpha = w * inv;
        float2 hv = ((const float2*)H)[(size_t)s * 32 + lane];
        a0 += alpha * hv.x; a1 += alpha * hv.y;
    }
    a0 += c0; a1 += c1;

    a0 = fmaxf(a0 + b.x, 0.f);
    a1 = fmaxf(a1 + b.y, 0.f);
    ((float2*)Out)[(size_t)d * 32 + lane] = make_float2(a0, a1);
}

// ---------------- mean pool per graph + final linear [64 x 2] ----------------
template <int HB>
__global__ void pool_kernel(const void* __restrict__ batch,
                            const float* __restrict__ Wlin,
                            const float* __restrict__ blin,
                            float* __restrict__ out, int N) {
    __shared__ float pooled[64];
    __shared__ int sb, se;
    const float* H = bufsel(HB);
    int g = blockIdx.x;
    if (threadIdx.x == 0) {
        int is64 = g_idx64;
        int lo = 0, hi = N;
        while (lo < hi) { int mid = (lo + hi) >> 1; if (loadIdx(batch, mid, is64) < g) lo = mid + 1; else hi = mid; }
        sb = lo;
        hi = N;
        while (lo < hi) { int mid = (lo + hi) >> 1; if (loadIdx(batch, mid, is64) < g + 1) lo = mid + 1; else hi = mid; }
        se = lo;
    }
    __syncthreads();
    int c = threadIdx.x;
    float acc = 0.f;
    int b0 = sb, b1 = se;
    for (int i = b0; i < b1; i++) acc += H[(size_t)i * 64 + c];
    float cnt = (float)max(b1 - b0, 1);
    pooled[c] = acc / cnt;
    __syncthreads();
    if (c < 2) {
        float o = blin[c];
#pragma unroll
        for (int k = 0; k < 64; k++) o += pooled[k] * Wlin[k * 2 + c];
        out[g * 2 + c] = o;
    }
}

// ---------------- launch ----------------
extern "C" void kernel_launch(void* const* d_in, const int* in_sizes, int n_in,
                              void* d_out, int out_size) {
    const float* x    = (const float*)d_in[0];
    const void*  ei   = d_in[1];
    const void*  batch= d_in[2];
    const float* W1   = (const float*)d_in[3];
    const float* as1  = (const float*)d_in[4];
    const float* ad1  = (const float*)d_in[5];
    const float* b1   = (const float*)d_in[6];
    const float* W2   = (const float*)d_in[7];
    const float* as2  = (const float*)d_in[8];
    const float* ad2  = (const float*)d_in[9];
    const float* b2   = (const float*)d_in[10];
    const float* Wlin = (const float*)d_in[11];
    const float* blin = (const float*)d_in[12];
    float* out = (float*)d_out;

    int N = in_sizes[2];
    int E = in_sizes[1] / 2;
    if (N > NMAX) N = NMAX;
    if (E + N > ETOTMAX) E = ETOTMAX - N;
    int G = out_size / 2;
    int tot = E + N;
    int nb = (N + SCANBLK - 1) / SCANBLK;

    int gemmBlocks = (N + 127) / 128;
    int aggBlocks  = (N + 7) / 8;

    cudaFuncSetAttribute(gemm_mma_kernel<12, -1, 0, 1>, cudaFuncAttributeMaxDynamicSharedMemorySize, G1SMEM);
    cudaFuncSetAttribute(gemm_mma_kernel<1, 1, 0, 2>, cudaFuncAttributeMaxDynamicSharedMemorySize, G1SMEM);

    // fork a second stream so CSR build overlaps gemm1 path
    cudaStream_t sB;
    cudaStreamCreateWithFlags(&sB, cudaStreamNonBlocking);
    cudaEvent_t eF, eJ;
    cudaEventCreateWithFlags(&eF, cudaEventDisableTiming);
    cudaEventCreateWithFlags(&eJ, cudaEventDisableTiming);
    cudaEventRecord(eF, 0);
    cudaStreamWaitEvent(sB, eF, 0);

    // ---- branch A (default stream): CSR build ----
    zero_detect_kernel<<<(N + 255) / 256, 256>>>(batch, N);
    hist_kernel<<<(tot + 255) / 256, 256>>>(ei, E, N);
    partial_scan_kernel<<<nb, SCANBLK>>>(N);
    scan_sums_kernel<<<1, 1024>>>(nb);
    add_off_kernel<<<(N + 255) / 256, 256>>>(N, tot);
    scatter_kernel<<<(tot + 255) / 256, 256>>>(ei, E, N);

    // ---- branch B (sB): fused weight prep + gemm1 (+ att1 fused) ----
    wprep_both_kernel<<<(W1ELEMS + W2ELEMS + 255) / 256, 256, 0, sB>>>(W1, W2);
    gemm_mma_kernel<12, -1, 0, 1><<<gemmBlocks, 256, G1SMEM, sB>>>(x, as1, ad1, N);

    // ---- join ----
    cudaEventRecord(eJ, sB);
    cudaStreamWaitEvent(0, eJ, 0);

    // layer 1 aggregate, then layer 2 (+ att2 fused), then pool
    agg_kernel<0, 1><<<aggBlocks, 256>>>(b1, N);
    gemm_mma_kernel<1, 1, 0, 2><<<gemmBlocks, 256, G1SMEM>>>(nullptr, as2, ad2, N);
    agg_kernel<0, 1><<<aggBlocks, 256>>>(b2, N);
    pool_kernel<1><<<G, 64>>>(batch, Wlin, blin, out, N);

    cudaEventDestroy(eF);
    cudaEventDestroy(eJ);
    cudaStreamDestroy(sB);
}

// round 13
// speedup vs baseline: 1.0996x; 1.0145x over previous
#include <cuda_runtime.h>
#include <cuda_bf16.h>
#include <math.h>

#define NEG_SLOPE 0.2f

// ---------------- device scratch (no allocations allowed) ----------------
#define NMAX 50000
#define ETOTMAX 850000
#define SCANBLK 256
#define MAXSB 1024
#define GMAX 1024

__device__ float g_bufA[NMAX * 64];
__device__ float g_bufB[NMAX * 64];
__device__ float g_as[NMAX];
__device__ float g_ad[NMAX];
__device__ float g_pool[GMAX * 64];
__device__ int   g_count[NMAX];
__device__ int   g_rowstart[NMAX + 1];
__device__ int   g_cursor[NMAX];
__device__ int   g_srcsorted[ETOTMAX];
__device__ int   g_blocksum[MAXSB];
__device__ int   g_blockoff[MAXSB];
__device__ int   g_idx64;
__device__ __nv_bfloat16 g_w1hi[64 * 768];
__device__ __nv_bfloat16 g_w1lo[64 * 768];
__device__ __nv_bfloat16 g_w2hi[64 * 64];
__device__ __nv_bfloat16 g_w2lo[64 * 64];

__device__ __forceinline__ float* bufsel(int id) { return id == 0 ? g_bufA : g_bufB; }

__device__ __forceinline__ int loadIdx(const void* p, long long i, int is64) {
    if (is64) return (int)((const long long*)p)[i];
    return ((const int*)p)[i];
}

// packed f32x2 -> bf16x2 (first arg lands in upper 16 bits, second in lower)
__device__ __forceinline__ unsigned cvt2bf(float hi, float lo) {
    unsigned r;
    asm("cvt.rn.bf16x2.f32 %0, %1, %2;" : "=r"(r) : "f"(hi), "f"(lo));
    return r;
}
__device__ __forceinline__ float bf_lo_as_f32(unsigned p) { return __uint_as_float(p << 16); }
__device__ __forceinline__ float bf_hi_as_f32(unsigned p) { return __uint_as_float(p & 0xFFFF0000u); }

// bf16 tensor-core MMA (sm_80+ path; compiles under compute_103)
__device__ __forceinline__ void mma_bf16(float* c, const unsigned* a, const unsigned* b) {
    asm volatile(
        "mma.sync.aligned.m16n8k16.row.col.f32.bf16.bf16.f32 "
        "{%0,%1,%2,%3}, {%4,%5,%6,%7}, {%8,%9}, {%0,%1,%2,%3};"
        : "+f"(c[0]), "+f"(c[1]), "+f"(c[2]), "+f"(c[3])
        : "r"(a[0]), "r"(a[1]), "r"(a[2]), "r"(a[3]), "r"(b[0]), "r"(b[1]));
}

// ---------------- zero counts + pool sums + dtype probe (fused) ----------------
__global__ void zero_detect_kernel(const void* __restrict__ batch, int N, int G) {
    int i = blockIdx.x * blockDim.x + threadIdx.x;
    if (i < N) g_count[i] = 0;
    if (i < G * 64) g_pool[i] = 0.f;
    if (blockIdx.x == 0) {
        __shared__ int nz;
        if (threadIdx.x == 0) nz = 0;
        __syncthreads();
        const int* w = (const int*)batch;
        int local = 0;
        for (int j = 1 + 2 * threadIdx.x; j < N; j += 2 * blockDim.x)
            if (w[j] != 0) local = 1;
        if (local) atomicOr(&nz, 1);
        __syncthreads();
        if (threadIdx.x == 0) g_idx64 = (nz == 0) ? 1 : 0;
    }
}

// ---------------- graph build ----------------
__global__ void hist_kernel(const void* __restrict__ ei, int E, int N) {
    int i = blockIdx.x * blockDim.x + threadIdx.x;
    int tot = E + N;
    if (i >= tot) return;
    int is64 = g_idx64;
    int dst = (i < E) ? loadIdx(ei, (long long)E + i, is64) : (i - E);
    atomicAdd(&g_count[dst], 1);
}

__global__ void partial_scan_kernel(int N) {
    __shared__ int wsum[8];
    int t = threadIdx.x;
    int idx = blockIdx.x * SCANBLK + t;
    int v = (idx < N) ? g_count[idx] : 0;
    int lane = t & 31, w = t >> 5;
    int s = v;
#pragma unroll
    for (int o = 1; o < 32; o <<= 1) {
        int u = __shfl_up_sync(0xffffffffu, s, o);
        if (lane >= o) s += u;
    }
    if (lane == 31) wsum[w] = s;
    __syncthreads();
    if (w == 0) {
        int ws = (lane < 8) ? wsum[lane] : 0;
#pragma unroll
        for (int o = 1; o < 8; o <<= 1) {
            int u = __shfl_up_sync(0xffffffffu, ws, o);
            if (lane >= o) ws += u;
        }
        if (lane < 8) wsum[lane] = ws;
    }
    __syncthreads();
    int incl = s + (w > 0 ? wsum[w - 1] : 0);
    if (idx < N) g_rowstart[idx] = incl - v;
    if (t == SCANBLK - 1) g_blocksum[blockIdx.x] = incl;
}

__global__ void scan_sums_kernel(int nb) {
    __shared__ int wsum[32];
    int t = threadIdx.x;
    int lane = t & 31, w = t >> 5;
    int v = (t < nb) ? g_blocksum[t] : 0;
    int s = v;
#pragma unroll
    for (int o = 1; o < 32; o <<= 1) {
        int u = __shfl_up_sync(0xffffffffu, s, o);
        if (lane >= o) s += u;
    }
    if (lane == 31) wsum[w] = s;
    __syncthreads();
    if (w == 0) {
        int ws = wsum[lane];
#pragma unroll
        for (int o = 1; o < 32; o <<= 1) {
            int u = __shfl_up_sync(0xffffffffu, ws, o);
            if (lane >= o) ws += u;
        }
        wsum[lane] = ws;
    }
    __syncthreads();
    int excl = s - v + (w > 0 ? wsum[w - 1] : 0);
    if (t < nb) g_blockoff[t] = excl;
}

__global__ void add_off_kernel(int N, int tot) {
    int idx = blockIdx.x * blockDim.x + threadIdx.x;
    if (idx < N) {
        int r = g_rowstart[idx] + g_blockoff[idx >> 8];
        g_rowstart[idx] = r;
        g_cursor[idx] = r;
    }
    if (idx == 0) g_rowstart[N] = tot;
}

__global__ void scatter_kernel(const void* __restrict__ ei, int E, int N) {
    int i = blockIdx.x * blockDim.x + threadIdx.x;
    int tot = E + N;
    if (i >= tot) return;
    int is64 = g_idx64;
    int src, dst;
    if (i < E) {
        src = loadIdx(ei, i, is64);
        dst = loadIdx(ei, (long long)E + i, is64);
    } else {
        src = i - E; dst = i - E;
    }
    int pos = atomicAdd(&g_cursor[dst], 1);
    g_srcsorted[pos] = src;
}

// ---------------- W prep (fused W1+W2): transpose + bf16 hi/lo split ----------------
#define W1ELEMS (768 * 64)
#define W2ELEMS (64 * 64)
__global__ void wprep_both_kernel(const float* __restrict__ W1, const float* __restrict__ W2) {
    int t = blockIdx.x * blockDim.x + threadIdx.x;
    if (t < W1ELEMS) {
        int k = t >> 6, n = t & 63;
        float v = W1[t];
        __nv_bfloat16 hi = __float2bfloat16(v);
        __nv_bfloat16 lo = __float2bfloat16(v - __bfloat162float(hi));
        g_w1hi[n * 768 + k] = hi;
        g_w1lo[n * 768 + k] = lo;
    } else if (t < W1ELEMS + W2ELEMS) {
        int u = t - W1ELEMS;
        int k = u >> 6, n = u & 63;
        float v = W2[u];
        __nv_bfloat16 hi = __float2bfloat16(v);
        __nv_bfloat16 lo = __float2bfloat16(v - __bfloat162float(hi));
        g_w2hi[n * 64 + k] = hi;
        g_w2lo[n * 64 + k] = lo;
    }
}

// ---------------- GEMM via mma.sync bf16x3 + fused attention scores ----------------
// occ 2, X+W register prefetch (proven configuration).
#define ASTR 144
#define G1SMEM (2 * 128 * ASTR + 2 * 64 * ASTR)   // 55296 B

template <int NKC, int XB, int DB, int WSel>
__global__ void __launch_bounds__(256, 2) gemm_mma_kernel(const float* __restrict__ Xext,
                                                          const float* __restrict__ att_s,
                                                          const float* __restrict__ att_d,
                                                          int nrows) {
    extern __shared__ char sm[];
    char* sAh = sm;
    char* sAl = sm + 128 * ASTR;
    char* sBh = sm + 2 * 128 * ASTR;
    char* sBl = sBh + 64 * ASTR;

    const int t = threadIdx.x;
    const int lane = t & 31, wid = t >> 5;
    const int g = lane >> 2, tg = lane & 3;
    const int wm = wid >> 1, wn = wid & 1;
    const int row0 = blockIdx.x * 128;

    const float* X = (XB < 0) ? Xext : bufsel(XB);
    float* OutBuf = bufsel(DB);
    const float4* X4 = (const float4*)X;
    const uint2* WH = (const uint2*)((WSel == 1) ? g_w1hi : g_w2hi);
    const uint2* WL = (const uint2*)((WSel == 1) ? g_w1lo : g_w2lo);

    float acc[2][4][4];
#pragma unroll
    for (int a = 0; a < 2; a++)
#pragma unroll
        for (int b = 0; b < 4; b++)
#pragma unroll
            for (int c = 0; c < 4; c++) acc[a][b][c] = 0.f;

    float4 px[8];
    uint2 pwh[4], pwl[4];

    auto loadX = [&](int kc) {
#pragma unroll
        for (int i = 0; i < 8; i++) {
            int idx = t + i * 256, r = idx >> 4, q = idx & 15;
            px[i] = (row0 + r < nrows) ? X4[(size_t)(row0 + r) * (NKC * 16) + kc * 16 + q]
                                       : make_float4(0.f, 0.f, 0.f, 0.f);
        }
    };
    auto loadW = [&](int kc) {
#pragma unroll
        for (int i = 0; i < 4; i++) {
            int idx = t + i * 256, n = idx >> 4, q = idx & 15;
            pwh[i] = WH[n * (NKC * 16) + kc * 16 + q];
            pwl[i] = WL[n * (NKC * 16) + kc * 16 + q];
        }
    };
    auto stage = [&]() {
#pragma unroll
        for (int i = 0; i < 8; i++) {
            int idx = t + i * 256, r = idx >> 4, q = idx & 15;
            float4 v = px[i];
            unsigned h01 = cvt2bf(v.y, v.x);
            unsigned h23 = cvt2bf(v.w, v.z);
            float l0 = v.x - bf_lo_as_f32(h01);
            float l1 = v.y - bf_hi_as_f32(h01);
            float l2 = v.z - bf_lo_as_f32(h23);
            float l3 = v.w - bf_hi_as_f32(h23);
            unsigned l01 = cvt2bf(l1, l0);
            unsigned l23 = cvt2bf(l3, l2);
            *(uint2*)(sAh + r * ASTR + q * 8) = make_uint2(h01, h23);
            *(uint2*)(sAl + r * ASTR + q * 8) = make_uint2(l01, l23);
        }
#pragma unroll
        for (int i = 0; i < 4; i++) {
            int idx = t + i * 256, n = idx >> 4, q = idx & 15;
            *(uint2*)(sBh + n * ASTR + q * 8) = pwh[i];
            *(uint2*)(sBl + n * ASTR + q * 8) = pwl[i];
        }
    };

    loadX(0); loadW(0);
    for (int kc = 0; kc < NKC; kc++) {
        stage();
        __syncthreads();
        if (kc < NKC - 1) { loadX(kc + 1); loadW(kc + 1); }
#pragma unroll
        for (int ks = 0; ks < 4; ks++) {
            unsigned ah[2][4], al[2][4];
#pragma unroll
            for (int mf = 0; mf < 2; mf++) {
                int roff = (wm * 32 + mf * 16 + g) * ASTR + ks * 32 + tg * 4;
                ah[mf][0] = *(const unsigned*)(sAh + roff);
                ah[mf][1] = *(const unsigned*)(sAh + roff + 8 * ASTR);
                ah[mf][2] = *(const unsigned*)(sAh + roff + 16);
                ah[mf][3] = *(const unsigned*)(sAh + roff + 8 * ASTR + 16);
                al[mf][0] = *(const unsigned*)(sAl + roff);
                al[mf][1] = *(const unsigned*)(sAl + roff + 8 * ASTR);
                al[mf][2] = *(const unsigned*)(sAl + roff + 16);
                al[mf][3] = *(const unsigned*)(sAl + roff + 8 * ASTR + 16);
            }
#pragma unroll
            for (int nf = 0; nf < 4; nf++) {
                int noff = (wn * 32 + nf * 8 + g) * ASTR + ks * 32 + tg * 4;
                unsigned bh[2], bl[2];
                bh[0] = *(const unsigned*)(sBh + noff);
                bh[1] = *(const unsigned*)(sBh + noff + 16);
                bl[0] = *(const unsigned*)(sBl + noff);
                bl[1] = *(const unsigned*)(sBl + noff + 16);
#pragma unroll
                for (int mf = 0; mf < 2; mf++) {
                    mma_bf16(acc[mf][nf], ah[mf], bh);
                    mma_bf16(acc[mf][nf], ah[mf], bl);
                    mma_bf16(acc[mf][nf], al[mf], bh);
                }
            }
        }
        __syncthreads();
    }

    // ---- epilogue: store D + fused attention scores ----
    float asc[8], adc[8];
#pragma unroll
    for (int nf = 0; nf < 4; nf++) {
        int c = wn * 32 + nf * 8 + tg * 2;
        asc[nf * 2] = att_s[c]; asc[nf * 2 + 1] = att_s[c + 1];
        adc[nf * 2] = att_d[c]; adc[nf * 2 + 1] = att_d[c + 1];
    }
    float* fS = (float*)sm;          // [128][2]
    float* fD = (float*)sm + 256;    // [128][2]

#pragma unroll
    for (int mf = 0; mf < 2; mf++) {
        int rbase = row0 + wm * 32 + mf * 16;
#pragma unroll
        for (int h = 0; h < 2; h++) {
            int r = rbase + g + h * 8;
            float ps = 0.f, pd = 0.f;
#pragma unroll
            for (int nf = 0; nf < 4; nf++) {
                float v0 = acc[mf][nf][h * 2], v1 = acc[mf][nf][h * 2 + 1];
                ps += v0 * asc[nf * 2] + v1 * asc[nf * 2 + 1];
                pd += v0 * adc[nf * 2] + v1 * adc[nf * 2 + 1];
            }
            ps += __shfl_xor_sync(0xffffffffu, ps, 1);
            ps += __shfl_xor_sync(0xffffffffu, ps, 2);
            pd += __shfl_xor_sync(0xffffffffu, pd, 1);
            pd += __shfl_xor_sync(0xffffffffu, pd, 2);
            int rl = wm * 32 + mf * 16 + h * 8 + g;
            if (tg == 0) {
                fS[rl * 2 + wn] = ps;
                fD[rl * 2 + wn] = pd;
            }
            if (r < nrows) {
                float* o = OutBuf + (size_t)r * 64 + wn * 32 + tg * 2;
#pragma unroll
                for (int nf = 0; nf < 4; nf++)
                    *(float2*)(o + nf * 8) = make_float2(acc[mf][nf][h * 2], acc[mf][nf][h * 2 + 1]);
            }
        }
    }
    __syncthreads();
    if (t < 128 && row0 + t < nrows) {
        g_as[row0 + t] = fS[t * 2] + fS[t * 2 + 1];
        g_ad[row0 + t] = fD[t * 2] + fD[t * 2 + 1];
    }
}

// ---------------- fused edge-softmax + aggregation ----------------
// POOL=0: write result row to buffer OB.  POOL=1: relu + atomicAdd into g_pool[batch[d]].
template <int HB, int OB, int POOL>
__global__ void __launch_bounds__(256) agg_kernel(const float* __restrict__ bias,
                                                  const void* __restrict__ batch, int N) {
    constexpr int CAP = 128;
    __shared__ float ce[8][CAP];
    __shared__ int   cs[8][CAP];
    const float* H = bufsel(HB);
    float* Out = bufsel(OB);

    int wl = threadIdx.x >> 5;
    int lane = threadIdx.x & 31;
    int d = blockIdx.x * 8 + wl;
    if (d >= N) return;

    int beg = g_rowstart[d], end = g_rowstart[d + 1];
    int deg = end - beg;
    float ad = g_ad[d];
    float2 b = ((const float2*)bias)[lane];

    float a0 = 0.f, a1 = 0.f;

    if (deg <= 32) {
        // ---- register fast path ----
        int s = 0;
        float e = -3.4e38f;
        if (lane < deg) {
            s = g_srcsorted[beg + lane];
            e = g_as[s] + ad;
            e = (e >= 0.f) ? e : NEG_SLOPE * e;
        }
        float mx = e;
#pragma unroll
        for (int o = 16; o; o >>= 1) mx = fmaxf(mx, __shfl_xor_sync(0xffffffffu, mx, o));
        float w = (lane < deg) ? __expf(e - mx) : 0.f;
        float sum = w;
#pragma unroll
        for (int o = 16; o; o >>= 1) sum += __shfl_xor_sync(0xffffffffu, sum, o);
        float inv = 1.0f / sum;

        float c0 = 0.f, c1 = 0.f;
        int j = 0;
        for (; j + 2 <= deg; j += 2) {
            float w0 = __shfl_sync(0xffffffffu, w, j);
            int   s0 = __shfl_sync(0xffffffffu, s, j);
            float w1 = __shfl_sync(0xffffffffu, w, j + 1);
            int   s1 = __shfl_sync(0xffffffffu, s, j + 1);
            float2 h0 = ((const float2*)H)[(size_t)s0 * 32 + lane];
            float2 h1 = ((const float2*)H)[(size_t)s1 * 32 + lane];
            float al0 = w0 * inv, al1 = w1 * inv;
            a0 += al0 * h0.x; a1 += al0 * h0.y;
            c0 += al1 * h1.x; c1 += al1 * h1.y;
        }
        if (j < deg) {
            float w0 = __shfl_sync(0xffffffffu, w, j);
            int   s0 = __shfl_sync(0xffffffffu, s, j);
            float2 h0 = ((const float2*)H)[(size_t)s0 * 32 + lane];
            float al0 = w0 * inv;
            a0 += al0 * h0.x; a1 += al0 * h0.y;
        }
        a0 += c0; a1 += c1;
    } else {
        // ---- smem slow path (deg > 32) ----
        float mx = -3.4e38f;
        for (int j = lane; j < deg; j += 32) {
            int s = g_srcsorted[beg + j];
            float e = g_as[s] + ad;
            e = (e >= 0.f) ? e : NEG_SLOPE * e;
            if (j < CAP) { ce[wl][j] = e; cs[wl][j] = s; }
            mx = fmaxf(mx, e);
        }
#pragma unroll
        for (int o = 16; o; o >>= 1) mx = fmaxf(mx, __shfl_xor_sync(0xffffffffu, mx, o));

        float sum = 0.f;
        for (int j = lane; j < deg; j += 32) {
            float e;
            if (j < CAP) e = ce[wl][j];
            else {
                int s = g_srcsorted[beg + j];
                e = g_as[s] + ad;
                e = (e >= 0.f) ? e : NEG_SLOPE * e;
            }
            float w = __expf(e - mx);
            if (j < CAP) ce[wl][j] = w;
            sum += w;
        }
#pragma unroll
        for (int o = 16; o; o >>= 1) sum += __shfl_xor_sync(0xffffffffu, sum, o);
        float inv = 1.0f / sum;
        __syncwarp();

        float c0 = 0.f, c1 = 0.f;
        int j = 0;
        for (; j + 2 <= deg; j += 2) {
            float w0, w1; int s0, s1;
            if (j < CAP) { w0 = ce[wl][j]; s0 = cs[wl][j]; }
            else {
                s0 = g_srcsorted[beg + j];
                float e = g_as[s0] + ad; e = (e >= 0.f) ? e : NEG_SLOPE * e;
                w0 = __expf(e - mx);
            }
            if (j + 1 < CAP) { w1 = ce[wl][j + 1]; s1 = cs[wl][j + 1]; }
            else {
                s1 = g_srcsorted[beg + j + 1];
                float e = g_as[s1] + ad; e = (e >= 0.f) ? e : NEG_SLOPE * e;
                w1 = __expf(e - mx);
            }
            float2 h0 = ((const float2*)H)[(size_t)s0 * 32 + lane];
            float2 h1 = ((const float2*)H)[(size_t)s1 * 32 + lane];
            float al0 = w0 * inv, al1 = w1 * inv;
            a0 += al0 * h0.x; a1 += al0 * h0.y;
            c0 += al1 * h1.x; c1 += al1 * h1.y;
        }
        if (j < deg) {
            float w; int s;
            if (j < CAP) { w = ce[wl][j]; s = cs[wl][j]; }
            else {
                s = g_srcsorted[beg + j];
                float e = g_as[s] + ad; e = (e >= 0.f) ? e : NEG_SLOPE * e;
                w = __expf(e - mx);
            }
            float alpha = w * inv;
            float2 hv = ((const float2*)H)[(size_t)s * 32 + lane];
            a0 += alpha * hv.x; a1 += alpha * hv.y;
        }
        a0 += c0; a1 += c1;
    }

    a0 = fmaxf(a0 + b.x, 0.f);
    a1 = fmaxf(a1 + b.y, 0.f);
    if (POOL) {
        int gg = loadIdx(batch, d, g_idx64);
        atomicAdd(&g_pool[gg * 64 + 2 * lane], a0);
        atomicAdd(&g_pool[gg * 64 + 2 * lane + 1], a1);
    } else {
        ((float2*)Out)[(size_t)d * 32 + lane] = make_float2(a0, a1);
    }
}

// ---------------- finalize: mean + linear [64 x 2] per graph ----------------
__global__ void finalize_kernel(const void* __restrict__ batch,
                                const float* __restrict__ Wlin,
                                const float* __restrict__ blin,
                                float* __restrict__ out, int N) {
    __shared__ float pooled[64];
    __shared__ int sb, se;
    int g = blockIdx.x;
    if (threadIdx.x == 0) {
        int is64 = g_idx64;
        int lo = 0, hi = N;
        while (lo < hi) { int mid = (lo + hi) >> 1; if (loadIdx(batch, mid, is64) < g) lo = mid + 1; else hi = mid; }
        sb = lo;
        hi = N;
        while (lo < hi) { int mid = (lo + hi) >> 1; if (loadIdx(batch, mid, is64) < g + 1) lo = mid + 1; else hi = mid; }
        se = lo;
    }
    __syncthreads();
    int c = threadIdx.x;  // 64 threads
    float cnt = (float)max(se - sb, 1);
    pooled[c] = g_pool[g * 64 + c] / cnt;
    __syncthreads();
    if (c < 2) {
        float o = blin[c];
#pragma unroll
        for (int k = 0; k < 64; k++) o += pooled[k] * Wlin[k * 2 + c];
        out[g * 2 + c] = o;
    }
}

// ---------------- launch ----------------
extern "C" void kernel_launch(void* const* d_in, const int* in_sizes, int n_in,
                              void* d_out, int out_size) {
    const float* x    = (const float*)d_in[0];
    const void*  ei   = d_in[1];
    const void*  batch= d_in[2];
    const float* W1   = (const float*)d_in[3];
    const float* as1  = (const float*)d_in[4];
    const float* ad1  = (const float*)d_in[5];
    const float* b1   = (const float*)d_in[6];
    const float* W2   = (const float*)d_in[7];
    const float* as2  = (const float*)d_in[8];
    const float* ad2  = (const float*)d_in[9];
    const float* b2   = (const float*)d_in[10];
    const float* Wlin = (const float*)d_in[11];
    const float* blin = (const float*)d_in[12];
    float* out = (float*)d_out;

    int N = in_sizes[2];
    int E = in_sizes[1] / 2;
    if (N > NMAX) N = NMAX;
    if (E + N > ETOTMAX) E = ETOTMAX - N;
    int G = out_size / 2;
    if (G > GMAX) G = GMAX;
    int tot = E + N;
    int nb = (N + SCANBLK - 1) / SCANBLK;

    int gemmBlocks = (N + 127) / 128;
    int aggBlocks  = (N + 7) / 8;

    cudaFuncSetAttribute(gemm_mma_kernel<12, -1, 0, 1>, cudaFuncAttributeMaxDynamicSharedMemorySize, G1SMEM);
    cudaFuncSetAttribute(gemm_mma_kernel<1, 1, 0, 2>, cudaFuncAttributeMaxDynamicSharedMemorySize, G1SMEM);

    // fork a second stream so CSR build overlaps gemm1 path
    cudaStream_t sB;
    cudaStreamCreateWithFlags(&sB, cudaStreamNonBlocking);
    cudaEvent_t eF, eJ;
    cudaEventCreateWithFlags(&eF, cudaEventDisableTiming);
    cudaEventCreateWithFlags(&eJ, cudaEventDisableTiming);
    cudaEventRecord(eF, 0);
    cudaStreamWaitEvent(sB, eF, 0);

    // ---- branch A (default stream): CSR build + pool zero ----
    int zdBlocks = (max(N, G * 64) + 255) / 256;
    zero_detect_kernel<<<zdBlocks, 256>>>(batch, N, G);
    hist_kernel<<<(tot + 255) / 256, 256>>>(ei, E, N);
    partial_scan_kernel<<<nb, SCANBLK>>>(N);
    scan_sums_kernel<<<1, 1024>>>(nb);
    add_off_kernel<<<(N + 255) / 256, 256>>>(N, tot);
    scatter_kernel<<<(tot + 255) / 256, 256>>>(ei, E, N);

    // ---- branch B (sB): fused weight prep + gemm1 (+ att1 fused) ----
    wprep_both_kernel<<<(W1ELEMS + W2ELEMS + 255) / 256, 256, 0, sB>>>(W1, W2);
    gemm_mma_kernel<12, -1, 0, 1><<<gemmBlocks, 256, G1SMEM, sB>>>(x, as1, ad1, N);

    // ---- join ----
    cudaEventRecord(eJ, sB);
    cudaStreamWaitEvent(0, eJ, 0);

    // layer 1 aggregate, then layer 2 (+ att2 fused), then agg2 (+pool fused), finalize
    agg_kernel<0, 1, 0><<<aggBlocks, 256>>>(b1, batch, N);
    gemm_mma_kernel<1, 1, 0, 2><<<gemmBlocks, 256, G1SMEM>>>(nullptr, as2, ad2, N);
    agg_kernel<0, 1, 1><<<aggBlocks, 256>>>(b2, batch, N);
    finalize_kernel<<<G, 64>>>(batch, Wlin, blin, out, N);

    cudaEventDestroy(eF);
    cudaEventDestroy(eJ);
    cudaStreamDestroy(sB);
}